// round 7
// baseline (speedup 1.0000x reference)
#include <cuda_runtime.h>
#include <math.h>

#define LN_EPS 1e-5f

// pre-activation scratch: [2][4096][4096] fp32 = 128 MB (static __device__, allowed)
__device__ float g_pre[2ull * 4096 * 4096];

// ---------------------------------------------------------------------------
// GEMM: C[m,n] = sum_k A[m,k] * W[n,k]   (both operands K-contiguous, "NT")
// M=N=4096, K=1024. blockIdx.z: 0 -> x @ w_ih^T, 1 -> h @ w_hh^T
// 128x128 tile, BK=16, 256 threads, 8x8 per-thread register tile.
// ---------------------------------------------------------------------------
__global__ __launch_bounds__(256) void gemm_nt_kernel(
    const float* __restrict__ X, const float* __restrict__ Hm,
    const float* __restrict__ Wih, const float* __restrict__ Whh)
{
    const int M = 4096, N = 4096, K = 1024;
    const float* A = blockIdx.z ? Hm  : X;
    const float* W = blockIdx.z ? Whh : Wih;
    float* C = g_pre + (size_t)blockIdx.z * M * N;

    __shared__ float As[16][132];   // +4 pad: kills STS bank conflicts
    __shared__ float Ws[16][132];

    const int tid = threadIdx.x;
    const int tx = tid & 15;        // 0..15  -> n sub-tile
    const int ty = tid >> 4;        // 0..15  -> m sub-tile
    const int m0 = blockIdx.y * 128;
    const int n0 = blockIdx.x * 128;

    float acc[8][8];
    #pragma unroll
    for (int i = 0; i < 8; i++)
        #pragma unroll
        for (int j = 0; j < 8; j++) acc[i][j] = 0.0f;

    for (int kt = 0; kt < K; kt += 16) {
        // ---- load 128x16 tiles of A and W (float4, coalesced) ----
        #pragma unroll
        for (int r = 0; r < 2; r++) {
            int idx = tid + r * 256;          // 0..511
            int row = idx >> 2;               // 0..127
            int kq  = (idx & 3) * 4;          // 0,4,8,12
            float4 va = *(const float4*)&A[(size_t)(m0 + row) * K + kt + kq];
            As[kq + 0][row] = va.x; As[kq + 1][row] = va.y;
            As[kq + 2][row] = va.z; As[kq + 3][row] = va.w;
            float4 vw = *(const float4*)&W[(size_t)(n0 + row) * K + kt + kq];
            Ws[kq + 0][row] = vw.x; Ws[kq + 1][row] = vw.y;
            Ws[kq + 2][row] = vw.z; Ws[kq + 3][row] = vw.w;
        }
        __syncthreads();

        // ---- 16 k-steps of 8x8 outer product ----
        #pragma unroll
        for (int kk = 0; kk < 16; kk++) {
            float a[8], b[8];
            *(float4*)&a[0] = *(const float4*)&As[kk][ty * 8];
            *(float4*)&a[4] = *(const float4*)&As[kk][ty * 8 + 4];
            *(float4*)&b[0] = *(const float4*)&Ws[kk][tx * 8];
            *(float4*)&b[4] = *(const float4*)&Ws[kk][tx * 8 + 4];
            #pragma unroll
            for (int i = 0; i < 8; i++)
                #pragma unroll
                for (int j = 0; j < 8; j++)
                    acc[i][j] = fmaf(a[i], b[j], acc[i][j]);
        }
        __syncthreads();
    }

    // ---- store 8x8 tile, float4 ----
    #pragma unroll
    for (int i = 0; i < 8; i++) {
        size_t base = (size_t)(m0 + ty * 8 + i) * N + n0 + tx * 8;
        *(float4*)&C[base]     = make_float4(acc[i][0], acc[i][1], acc[i][2], acc[i][3]);
        *(float4*)&C[base + 4] = make_float4(acc[i][4], acc[i][5], acc[i][6], acc[i][7]);
    }
}

// ---------------------------------------------------------------------------
// block reduction of 4 floats across 256 threads
// ---------------------------------------------------------------------------
__device__ __forceinline__ float4 blockReduce4(float4 v)
{
    __shared__ float sb[8][4];
    const unsigned m = 0xffffffffu;
    #pragma unroll
    for (int o = 16; o > 0; o >>= 1) {
        v.x += __shfl_down_sync(m, v.x, o);
        v.y += __shfl_down_sync(m, v.y, o);
        v.z += __shfl_down_sync(m, v.z, o);
        v.w += __shfl_down_sync(m, v.w, o);
    }
    int lane = threadIdx.x & 31, warp = threadIdx.x >> 5;
    __syncthreads();                 // protect sb from previous call
    if (lane == 0) { sb[warp][0] = v.x; sb[warp][1] = v.y; sb[warp][2] = v.z; sb[warp][3] = v.w; }
    __syncthreads();
    float4 r = make_float4(0.f, 0.f, 0.f, 0.f);
    #pragma unroll
    for (int w = 0; w < 8; w++) {
        r.x += sb[w][0]; r.y += sb[w][1]; r.z += sb[w][2]; r.w += sb[w][3];
    }
    return r;
}

__device__ __forceinline__ float sigf(float x) { return 1.0f / (1.0f + expf(-x)); }

// ---------------------------------------------------------------------------
// Fused LN + gates + cell update. One CTA (256 thr) per batch row.
// gate g: LN(pre_ih, gamma[2g], beta[2g]) + LN(pre_hh, gamma[2g+1], beta[2g+1]) + b_ih
// c_new = sig(f)*c + sig(i)*tanh(a);  h_new = sig(o)*tanh(LN(c_new, row 8))
// out layout: [h_new (B*H)] then [c_new (B*H)]
// ---------------------------------------------------------------------------
__global__ __launch_bounds__(256) void lstm_epi_kernel(
    const float* __restrict__ cin, const float* __restrict__ b_ih,
    const float* __restrict__ gamma, const float* __restrict__ beta,
    float* __restrict__ out)
{
    const int H = 1024, B = 4096;
    const int b = blockIdx.x;
    const int j = threadIdx.x * 4;          // 4 contiguous elems per thread
    const float invH = 1.0f / (float)H;

    const float* pih = g_pre + (size_t)b * 4096;                       // pre_ih row b
    const float* phh = g_pre + (size_t)4096 * 4096 + (size_t)b * 4096; // pre_hh row b

    float gate[4][4];

    #pragma unroll
    for (int g = 0; g < 4; g++) {
        float4 ti = *(const float4*)&pih[g * H + j];
        float4 th = *(const float4*)&phh[g * H + j];
        float vi[4] = { ti.x, ti.y, ti.z, ti.w };
        float vh[4] = { th.x, th.y, th.z, th.w };

        float4 part;
        part.x = vi[0] + vi[1] + vi[2] + vi[3];
        part.y = vi[0]*vi[0] + vi[1]*vi[1] + vi[2]*vi[2] + vi[3]*vi[3];
        part.z = vh[0] + vh[1] + vh[2] + vh[3];
        part.w = vh[0]*vh[0] + vh[1]*vh[1] + vh[2]*vh[2] + vh[3]*vh[3];
        float4 tot = blockReduce4(part);

        float mi = tot.x * invH;
        float ri = rsqrtf(tot.y * invH - mi * mi + LN_EPS);
        float mh = tot.z * invH;
        float rh = rsqrtf(tot.w * invH - mh * mh + LN_EPS);

        float4 gi4 = *(const float4*)&gamma[(2 * g) * H + j];
        float4 bi4 = *(const float4*)&beta [(2 * g) * H + j];
        float4 gh4 = *(const float4*)&gamma[(2 * g + 1) * H + j];
        float4 bh4 = *(const float4*)&beta [(2 * g + 1) * H + j];
        float4 bb4 = *(const float4*)&b_ih [g * H + j];
        float gi[4] = { gi4.x, gi4.y, gi4.z, gi4.w };
        float bi[4] = { bi4.x, bi4.y, bi4.z, bi4.w };
        float gh[4] = { gh4.x, gh4.y, gh4.z, gh4.w };
        float bh[4] = { bh4.x, bh4.y, bh4.z, bh4.w };
        float bb[4] = { bb4.x, bb4.y, bb4.z, bb4.w };

        #pragma unroll
        for (int u = 0; u < 4; u++)
            gate[g][u] = gi[u] * (vi[u] - mi) * ri + bi[u]
                       + gh[u] * (vh[u] - mh) * rh + bh[u]
                       + bb[u];
    }

    // cell update
    float4 cv4 = *(const float4*)&cin[(size_t)b * H + j];
    float cv[4] = { cv4.x, cv4.y, cv4.z, cv4.w };
    float cn[4];
    #pragma unroll
    for (int u = 0; u < 4; u++)
        cn[u] = sigf(gate[1][u]) * cv[u] + sigf(gate[0][u]) * tanhf(gate[2][u]);

    float4 pc;
    pc.x = cn[0] + cn[1] + cn[2] + cn[3];
    pc.y = cn[0]*cn[0] + cn[1]*cn[1] + cn[2]*cn[2] + cn[3]*cn[3];
    pc.z = 0.f; pc.w = 0.f;
    float4 tc = blockReduce4(pc);
    float mc = tc.x * invH;
    float rc = rsqrtf(tc.y * invH - mc * mc + LN_EPS);

    float4 g84 = *(const float4*)&gamma[8 * H + j];
    float4 b84 = *(const float4*)&beta [8 * H + j];
    float g8[4] = { g84.x, g84.y, g84.z, g84.w };
    float b8[4] = { b84.x, b84.y, b84.z, b84.w };

    float hn[4];
    #pragma unroll
    for (int u = 0; u < 4; u++) {
        float lnc = g8[u] * (cn[u] - mc) * rc + b8[u];
        hn[u] = sigf(gate[3][u]) * tanhf(lnc);
    }

    *(float4*)&out[(size_t)b * H + j] = make_float4(hn[0], hn[1], hn[2], hn[3]);
    *(float4*)&out[(size_t)B * H + (size_t)b * H + j] = make_float4(cn[0], cn[1], cn[2], cn[3]);
}

// ---------------------------------------------------------------------------
// inputs (metadata order): x, h, c, w_ih, w_hh, b_ih, ln_gamma, ln_beta, time
// ---------------------------------------------------------------------------
extern "C" void kernel_launch(void* const* d_in, const int* in_sizes, int n_in,
                              void* d_out, int out_size)
{
    const float* x     = (const float*)d_in[0];
    const float* h     = (const float*)d_in[1];
    const float* c     = (const float*)d_in[2];
    const float* w_ih  = (const float*)d_in[3];
    const float* w_hh  = (const float*)d_in[4];
    const float* b_ih  = (const float*)d_in[5];
    const float* gamma = (const float*)d_in[6];
    const float* beta  = (const float*)d_in[7];
    float* out = (float*)d_out;

    dim3 grid(32, 32, 2);          // 4096/128 x 4096/128 x {ih, hh}
    gemm_nt_kernel<<<grid, 256>>>(x, h, w_ih, w_hh);
    lstm_epi_kernel<<<4096, 256>>>(c, b_ih, gamma, beta, out);
}

// round 9
// speedup vs baseline: 2.6493x; 2.6493x over previous
#include <cuda_runtime.h>
#include <cuda_bf16.h>
#include <stdint.h>
#include <math.h>

#define LN_EPS 1e-5f

// ---------------------------------------------------------------------------
// Device scratch (static __device__ globals: allocation-guard safe)
// ---------------------------------------------------------------------------
__device__ __align__(1024) float g_pre[2ull * 4096 * 4096];                 // 128 MB
__device__ __align__(1024) __nv_bfloat16 g_A2[2ull * 4096 * 3072];          // 48 MB (x,h split)
__device__ __align__(1024) __nv_bfloat16 g_W2[2ull * 4096 * 3072];          // 48 MB (w_ih,w_hh split)

// ---------------------------------------------------------------------------
// helpers
// ---------------------------------------------------------------------------
__device__ __forceinline__ uint32_t smem_u32(const void* p) {
    uint32_t a;
    asm("{ .reg .u64 t; cvta.to.shared.u64 t, %1; cvt.u32.u64 %0, t; }" : "=r"(a) : "l"(p));
    return a;
}
__device__ __forceinline__ void cp_async16(uint32_t dst, const void* src) {
    asm volatile("cp.async.cg.shared.global [%0], [%1], 16;\n" :: "r"(dst), "l"(src));
}
#define CP_COMMIT() asm volatile("cp.async.commit_group;\n" ::: "memory")
#define CP_WAIT2()  asm volatile("cp.async.wait_group 2;\n" ::: "memory")

__device__ __forceinline__ uint32_t sw128(uint32_t off) { return off ^ ((off >> 3) & 0x70); }

__device__ __forceinline__ void ldsm_x4(uint32_t& r0, uint32_t& r1, uint32_t& r2, uint32_t& r3,
                                        uint32_t addr) {
    asm volatile("ldmatrix.sync.aligned.m8n8.x4.shared.b16 {%0,%1,%2,%3}, [%4];"
                 : "=r"(r0), "=r"(r1), "=r"(r2), "=r"(r3) : "r"(addr));
}
__device__ __forceinline__ void mma_bf16(float& c0, float& c1, float& c2, float& c3,
                                         uint32_t a0, uint32_t a1, uint32_t a2, uint32_t a3,
                                         uint32_t b0, uint32_t b1) {
    asm volatile("mma.sync.aligned.m16n8k16.row.col.f32.bf16.bf16.f32 "
                 "{%0,%1,%2,%3}, {%4,%5,%6,%7}, {%8,%9}, {%0,%1,%2,%3};"
                 : "+f"(c0), "+f"(c1), "+f"(c2), "+f"(c3)
                 : "r"(a0), "r"(a1), "r"(a2), "r"(a3), "r"(b0), "r"(b1));
}

// ---------------------------------------------------------------------------
// Split fp32 -> (hi, lo) bf16, laid out for a single K'=3072 GEMM.
// A-pattern (x, h):     [hi | hi | lo]
// W-pattern (w_ih/hh):  [hi | lo | hi]
// sum = Ahi*Whi + Ahi*Wlo + Alo*Whi   (drops Alo*Wlo ~ 4e-6 rel)
// ---------------------------------------------------------------------------
__global__ __launch_bounds__(256) void split_bf16_kernel(
    const float* __restrict__ x, const float* __restrict__ h,
    const float* __restrict__ wih, const float* __restrict__ whh)
{
    int z = blockIdx.z;
    const float* src = (z == 0) ? x : (z == 1) ? h : (z == 2) ? wih : whh;
    __nv_bfloat16* dst = (z < 2) ? (g_A2 + (size_t)z * 4096 * 3072)
                                 : (g_W2 + (size_t)(z - 2) * 4096 * 3072);
    int idx = blockIdx.x * 256 + threadIdx.x;
    int row = idx >> 8;
    int col = (idx & 255) * 4;
    float4 v = *(const float4*)&src[(size_t)row * 1024 + col];
    float vv[4] = { v.x, v.y, v.z, v.w };
    unsigned short hs[4], ls[4];
#pragma unroll
    for (int u = 0; u < 4; u++) {
        __nv_bfloat16 hb = __float2bfloat16(vv[u]);
        __nv_bfloat16 lb = __float2bfloat16(vv[u] - __bfloat162float(hb));
        hs[u] = __bfloat16_as_ushort(hb);
        ls[u] = __bfloat16_as_ushort(lb);
    }
    uint2 hv = make_uint2((uint32_t)hs[0] | ((uint32_t)hs[1] << 16),
                          (uint32_t)hs[2] | ((uint32_t)hs[3] << 16));
    uint2 lv = make_uint2((uint32_t)ls[0] | ((uint32_t)ls[1] << 16),
                          (uint32_t)ls[2] | ((uint32_t)ls[3] << 16));
    size_t rb = (size_t)row * 3072;
    if (z < 2) {   // A: hi | hi | lo
        *(uint2*)&dst[rb + col]        = hv;
        *(uint2*)&dst[rb + 1024 + col] = hv;
        *(uint2*)&dst[rb + 2048 + col] = lv;
    } else {       // W: hi | lo | hi
        *(uint2*)&dst[rb + col]        = hv;
        *(uint2*)&dst[rb + 1024 + col] = lv;
        *(uint2*)&dst[rb + 2048 + col] = hv;
    }
}

// ---------------------------------------------------------------------------
// bf16 NT GEMM via mma.sync: C[m,n] = sum_k A[m,k]*B[n,k], M=N=4096, K'=3072.
// CTA 128x256, BK=64 (one SW128 atom row), 3-stage cp.async pipeline.
// 8 warps: 2(m) x 4(n), warp tile 64x64. blockIdx.z -> (x,w_ih)/(h,w_hh).
// ---------------------------------------------------------------------------
#define BM 128
#define BN 256
#define BK 64
#define NCHUNK 48                     // 3072 / 64
#define A_BYTES (BM * 128)            // 16 KB
#define B_BYTES (BN * 128)            // 32 KB
#define STAGE_BYTES (A_BYTES + B_BYTES)
#define SMEM_DYN (3 * STAGE_BYTES + 1024)

__device__ __forceinline__ void load_chunk(uint32_t aBase, uint32_t bBase,
                                           const char* Ag, const char* Bg,
                                           int m0, int n0, int kc, int tid)
{
#pragma unroll
    for (int i = 0; i < 4; i++) {                 // A: 128 rows x 8 segs = 1024
        int idx = tid + i * 256;
        int row = idx >> 3;
        int seg = idx & 7;
        uint32_t soff = sw128((uint32_t)(row * 128 + seg * 16));
        cp_async16(aBase + soff, Ag + (size_t)(m0 + row) * 6144 + kc * 128 + seg * 16);
    }
#pragma unroll
    for (int i = 0; i < 8; i++) {                 // B: 256 rows x 8 segs = 2048
        int idx = tid + i * 256;
        int row = idx >> 3;
        int seg = idx & 7;
        uint32_t soff = sw128((uint32_t)(row * 128 + seg * 16));
        cp_async16(bBase + soff, Bg + (size_t)(n0 + row) * 6144 + kc * 128 + seg * 16);
    }
}

__global__ __launch_bounds__(256, 1) void gemm_mma_kernel()
{
    extern __shared__ char dynsmem[];

    const int tid  = threadIdx.x;
    const int wid  = tid >> 5;
    const int lane = tid & 31;
    const int z  = blockIdx.z;
    const int m0 = blockIdx.y * BM;
    const int n0 = blockIdx.x * BN;

    const char* Ag = (const char*)(g_A2 + (size_t)z * 4096 * 3072);
    const char* Bg = (const char*)(g_W2 + (size_t)z * 4096 * 3072);
    float* C = g_pre + (size_t)z * 4096 * 4096;

    const int warp_m = wid & 1;        // 0..1  -> m offset 0 / 64
    const int warp_n = wid >> 1;       // 0..3  -> n offset 0 / 64 / 128 / 192

    uint32_t base = (smem_u32(dynsmem) + 1023u) & ~1023u;

    // per-lane ldmatrix address components (within tile, pre-swizzle)
    const int ar = warp_m * 64 + (lane & 7) + (((lane >> 3) & 1) << 3); // A row (+mi*16)
    const int ah = (lane >> 4) & 1;                                     // A k-half (+16B)
    const int br = warp_n * 64 + (lane & 7) + (((lane >> 4) & 1) << 3); // B row (+pi*16)
    const int bh = (lane >> 3) & 1;                                     // B k-half

    float acc[4][8][4];
#pragma unroll
    for (int mi = 0; mi < 4; mi++)
#pragma unroll
        for (int oc = 0; oc < 8; oc++)
#pragma unroll
            for (int q = 0; q < 4; q++) acc[mi][oc][q] = 0.0f;

    // prologue: stages 0..2 <- chunks 0..2
#pragma unroll
    for (int s = 0; s < 3; s++) {
        load_chunk(base + s * STAGE_BYTES, base + s * STAGE_BYTES + A_BYTES,
                   Ag, Bg, m0, n0, s, tid);
        CP_COMMIT();
    }

    for (int c = 0; c < NCHUNK; c++) {
        const uint32_t stg = base + (uint32_t)(c % 3) * STAGE_BYTES;
        const uint32_t aB = stg;
        const uint32_t bB = stg + A_BYTES;

        CP_WAIT2();
        __syncthreads();               // chunk c resident for all warps

#pragma unroll
        for (int ks = 0; ks < 4; ks++) {
            uint32_t a[4][4], b[4][4];
#pragma unroll
            for (int mi = 0; mi < 4; mi++) {
                uint32_t off = (uint32_t)((ar + mi * 16) * 128 + ks * 32 + ah * 16);
                ldsm_x4(a[mi][0], a[mi][1], a[mi][2], a[mi][3], aB + sw128(off));
            }
#pragma unroll
            for (int pi = 0; pi < 4; pi++) {
                uint32_t off = (uint32_t)((br + pi * 16) * 128 + ks * 32 + bh * 16);
                ldsm_x4(b[pi][0], b[pi][1], b[pi][2], b[pi][3], bB + sw128(off));
            }
#pragma unroll
            for (int mi = 0; mi < 4; mi++)
#pragma unroll
                for (int oc = 0; oc < 8; oc++) {
                    uint32_t b0 = b[oc >> 1][(oc & 1) * 2];
                    uint32_t b1 = b[oc >> 1][(oc & 1) * 2 + 1];
                    mma_bf16(acc[mi][oc][0], acc[mi][oc][1], acc[mi][oc][2], acc[mi][oc][3],
                             a[mi][0], a[mi][1], a[mi][2], a[mi][3], b0, b1);
                }
        }

        __syncthreads();               // everyone done reading stage before refill
        if (c + 3 < NCHUNK)
            load_chunk(aB, bB, Ag, Bg, m0, n0, c + 3, tid);
        CP_COMMIT();                   // uniform group accounting (empty ok)
    }

    // epilogue: direct fp32 stores (quad-contiguous float2 -> full 32B sectors)
    const int rbase = m0 + warp_m * 64 + (lane >> 2);
    const int cbase = n0 + warp_n * 64 + (lane & 3) * 2;
#pragma unroll
    for (int mi = 0; mi < 4; mi++) {
#pragma unroll
        for (int oc = 0; oc < 8; oc++) {
            size_t r0 = (size_t)(rbase + mi * 16) * 4096 + cbase + oc * 8;
            size_t r1 = (size_t)(rbase + mi * 16 + 8) * 4096 + cbase + oc * 8;
            *(float2*)&C[r0] = make_float2(acc[mi][oc][0], acc[mi][oc][1]);
            *(float2*)&C[r1] = make_float2(acc[mi][oc][2], acc[mi][oc][3]);
        }
    }
}

// ---------------------------------------------------------------------------
// block reduction of 4 floats across 256 threads
// ---------------------------------------------------------------------------
__device__ __forceinline__ float4 blockReduce4(float4 v)
{
    __shared__ float sb[8][4];
    const unsigned m = 0xffffffffu;
#pragma unroll
    for (int o = 16; o > 0; o >>= 1) {
        v.x += __shfl_down_sync(m, v.x, o);
        v.y += __shfl_down_sync(m, v.y, o);
        v.z += __shfl_down_sync(m, v.z, o);
        v.w += __shfl_down_sync(m, v.w, o);
    }
    int lane = threadIdx.x & 31, warp = threadIdx.x >> 5;
    __syncthreads();
    if (lane == 0) { sb[warp][0] = v.x; sb[warp][1] = v.y; sb[warp][2] = v.z; sb[warp][3] = v.w; }
    __syncthreads();
    float4 r = make_float4(0.f, 0.f, 0.f, 0.f);
#pragma unroll
    for (int w = 0; w < 8; w++) {
        r.x += sb[w][0]; r.y += sb[w][1]; r.z += sb[w][2]; r.w += sb[w][3];
    }
    return r;
}

__device__ __forceinline__ float sigf(float x) { return 1.0f / (1.0f + expf(-x)); }

// ---------------------------------------------------------------------------
// Fused LN + gates + cell update. One CTA (256 thr) per batch row.
// ---------------------------------------------------------------------------
__global__ __launch_bounds__(256) void lstm_epi_kernel(
    const float* __restrict__ cin, const float* __restrict__ b_ih,
    const float* __restrict__ gamma, const float* __restrict__ beta,
    float* __restrict__ out)
{
    const int H = 1024, B = 4096;
    const int b = blockIdx.x;
    const int j = threadIdx.x * 4;
    const float invH = 1.0f / (float)H;

    const float* pih = g_pre + (size_t)b * 4096;
    const float* phh = g_pre + (size_t)4096 * 4096 + (size_t)b * 4096;

    float gate[4][4];

#pragma unroll
    for (int g = 0; g < 4; g++) {
        float4 ti = *(const float4*)&pih[g * H + j];
        float4 th = *(const float4*)&phh[g * H + j];
        float vi[4] = { ti.x, ti.y, ti.z, ti.w };
        float vh[4] = { th.x, th.y, th.z, th.w };

        float4 part;
        part.x = vi[0] + vi[1] + vi[2] + vi[3];
        part.y = vi[0]*vi[0] + vi[1]*vi[1] + vi[2]*vi[2] + vi[3]*vi[3];
        part.z = vh[0] + vh[1] + vh[2] + vh[3];
        part.w = vh[0]*vh[0] + vh[1]*vh[1] + vh[2]*vh[2] + vh[3]*vh[3];
        float4 tot = blockReduce4(part);

        float mi = tot.x * invH;
        float ri = rsqrtf(tot.y * invH - mi * mi + LN_EPS);
        float mh = tot.z * invH;
        float rh = rsqrtf(tot.w * invH - mh * mh + LN_EPS);

        float4 gi4 = *(const float4*)&gamma[(2 * g) * H + j];
        float4 bi4 = *(const float4*)&beta [(2 * g) * H + j];
        float4 gh4 = *(const float4*)&gamma[(2 * g + 1) * H + j];
        float4 bh4 = *(const float4*)&beta [(2 * g + 1) * H + j];
        float4 bb4 = *(const float4*)&b_ih [g * H + j];
        float gi[4] = { gi4.x, gi4.y, gi4.z, gi4.w };
        float bi[4] = { bi4.x, bi4.y, bi4.z, bi4.w };
        float gh[4] = { gh4.x, gh4.y, gh4.z, gh4.w };
        float bh[4] = { bh4.x, bh4.y, bh4.z, bh4.w };
        float bb[4] = { bb4.x, bb4.y, bb4.z, bb4.w };

#pragma unroll
        for (int u = 0; u < 4; u++)
            gate[g][u] = gi[u] * (vi[u] - mi) * ri + bi[u]
                       + gh[u] * (vh[u] - mh) * rh + bh[u]
                       + bb[u];
    }

    float4 cv4 = *(const float4*)&cin[(size_t)b * H + j];
    float cv[4] = { cv4.x, cv4.y, cv4.z, cv4.w };
    float cn[4];
#pragma unroll
    for (int u = 0; u < 4; u++)
        cn[u] = sigf(gate[1][u]) * cv[u] + sigf(gate[0][u]) * tanhf(gate[2][u]);

    float4 pc;
    pc.x = cn[0] + cn[1] + cn[2] + cn[3];
    pc.y = cn[0]*cn[0] + cn[1]*cn[1] + cn[2]*cn[2] + cn[3]*cn[3];
    pc.z = 0.f; pc.w = 0.f;
    float4 tc = blockReduce4(pc);
    float mc = tc.x * invH;
    float rc = rsqrtf(tc.y * invH - mc * mc + LN_EPS);

    float4 g84 = *(const float4*)&gamma[8 * H + j];
    float4 b84 = *(const float4*)&beta [8 * H + j];
    float g8[4] = { g84.x, g84.y, g84.z, g84.w };
    float b8[4] = { b84.x, b84.y, b84.z, b84.w };

    float hn[4];
#pragma unroll
    for (int u = 0; u < 4; u++) {
        float lnc = g8[u] * (cn[u] - mc) * rc + b8[u];
        hn[u] = sigf(gate[3][u]) * tanhf(lnc);
    }

    *(float4*)&out[(size_t)b * H + j] = make_float4(hn[0], hn[1], hn[2], hn[3]);
    *(float4*)&out[(size_t)B * H + (size_t)b * H + j] = make_float4(cn[0], cn[1], cn[2], cn[3]);
}

// ---------------------------------------------------------------------------
// inputs (metadata order): x, h, c, w_ih, w_hh, b_ih, ln_gamma, ln_beta, time
// ---------------------------------------------------------------------------
extern "C" void kernel_launch(void* const* d_in, const int* in_sizes, int n_in,
                              void* d_out, int out_size)
{
    const float* x     = (const float*)d_in[0];
    const float* h     = (const float*)d_in[1];
    const float* c     = (const float*)d_in[2];
    const float* w_ih  = (const float*)d_in[3];
    const float* w_hh  = (const float*)d_in[4];
    const float* b_ih  = (const float*)d_in[5];
    const float* gamma = (const float*)d_in[6];
    const float* beta  = (const float*)d_in[7];
    float* out = (float*)d_out;

    cudaFuncSetAttribute(gemm_mma_kernel,
                         cudaFuncAttributeMaxDynamicSharedMemorySize, SMEM_DYN);

    split_bf16_kernel<<<dim3(4096, 1, 4), 256>>>(x, h, w_ih, w_hh);
    gemm_mma_kernel<<<dim3(16, 32, 2), 256, SMEM_DYN>>>();
    lstm_epi_kernel<<<4096, 256>>>(c, b_ih, gamma, beta, out);
}

// round 13
// speedup vs baseline: 2.7429x; 1.0353x over previous
#include <cuda_runtime.h>
#include <cuda_bf16.h>
#include <stdint.h>
#include <math.h>

#define LN_EPS 1e-5f

// ---------------------------------------------------------------------------
// Device scratch (static __device__ globals: allocation-guard safe)
// Physical layout for A2/W2: [hi(1024) | lo(1024)] per row -> 2048 bf16 cols.
// ---------------------------------------------------------------------------
__device__ __align__(1024) float g_pre[2ull * 4096 * 4096];                 // 128 MB
__device__ __align__(1024) __nv_bfloat16 g_A2[2ull * 4096 * 2048];          // 32 MB (x,h split)
__device__ __align__(1024) __nv_bfloat16 g_W2[2ull * 4096 * 2048];          // 32 MB (w_ih,w_hh split)

// ---------------------------------------------------------------------------
// helpers
// ---------------------------------------------------------------------------
__device__ __forceinline__ uint32_t smem_u32(const void* p) {
    uint32_t a;
    asm("{ .reg .u64 t; cvta.to.shared.u64 t, %1; cvt.u32.u64 %0, t; }" : "=r"(a) : "l"(p));
    return a;
}
__device__ __forceinline__ void cp_async16(uint32_t dst, const void* src) {
    asm volatile("cp.async.cg.shared.global [%0], [%1], 16;\n" :: "r"(dst), "l"(src));
}
#define CP_COMMIT() asm volatile("cp.async.commit_group;\n" ::: "memory")
#define CP_WAIT2()  asm volatile("cp.async.wait_group 2;\n" ::: "memory")

__device__ __forceinline__ uint32_t sw128(uint32_t off) { return off ^ ((off >> 3) & 0x70); }

__device__ __forceinline__ void ldsm_x4(uint32_t& r0, uint32_t& r1, uint32_t& r2, uint32_t& r3,
                                        uint32_t addr) {
    asm volatile("ldmatrix.sync.aligned.m8n8.x4.shared.b16 {%0,%1,%2,%3}, [%4];"
                 : "=r"(r0), "=r"(r1), "=r"(r2), "=r"(r3) : "r"(addr));
}
__device__ __forceinline__ void mma_bf16(float& c0, float& c1, float& c2, float& c3,
                                         uint32_t a0, uint32_t a1, uint32_t a2, uint32_t a3,
                                         uint32_t b0, uint32_t b1) {
    asm volatile("mma.sync.aligned.m16n8k16.row.col.f32.bf16.bf16.f32 "
                 "{%0,%1,%2,%3}, {%4,%5,%6,%7}, {%8,%9}, {%0,%1,%2,%3};"
                 : "+f"(c0), "+f"(c1), "+f"(c2), "+f"(c3)
                 : "r"(a0), "r"(a1), "r"(a2), "r"(a3), "r"(b0), "r"(b1));
}

// ---------------------------------------------------------------------------
// Split fp32 -> (hi, lo) bf16, physical layout [hi | lo] (2048 cols).
// Logical K'=3072 GEMM reads: A pattern [hi|hi|lo], W pattern [hi|lo|hi]
// via chunk remapping in load_chunk. sum = Ahi*Whi + Ahi*Wlo + Alo*Whi.
// ---------------------------------------------------------------------------
__global__ __launch_bounds__(256) void split_bf16_kernel(
    const float* __restrict__ x, const float* __restrict__ h,
    const float* __restrict__ wih, const float* __restrict__ whh)
{
    int z = blockIdx.z;
    const float* src = (z == 0) ? x : (z == 1) ? h : (z == 2) ? wih : whh;
    __nv_bfloat16* dst = (z < 2) ? (g_A2 + (size_t)z * 4096 * 2048)
                                 : (g_W2 + (size_t)(z - 2) * 4096 * 2048);
    int idx = blockIdx.x * 256 + threadIdx.x;
    int row = idx >> 8;
    int col = (idx & 255) * 4;
    float4 v = *(const float4*)&src[(size_t)row * 1024 + col];
    float vv[4] = { v.x, v.y, v.z, v.w };
    unsigned short hs[4], ls[4];
#pragma unroll
    for (int u = 0; u < 4; u++) {
        __nv_bfloat16 hb = __float2bfloat16(vv[u]);
        __nv_bfloat16 lb = __float2bfloat16(vv[u] - __bfloat162float(hb));
        hs[u] = __bfloat16_as_ushort(hb);
        ls[u] = __bfloat16_as_ushort(lb);
    }
    uint2 hv = make_uint2((uint32_t)hs[0] | ((uint32_t)hs[1] << 16),
                          (uint32_t)hs[2] | ((uint32_t)hs[3] << 16));
    uint2 lv = make_uint2((uint32_t)ls[0] | ((uint32_t)ls[1] << 16),
                          (uint32_t)ls[2] | ((uint32_t)ls[3] << 16));
    size_t rb = (size_t)row * 2048;
    *(uint2*)&dst[rb + col]        = hv;
    *(uint2*)&dst[rb + 1024 + col] = lv;
}

// ---------------------------------------------------------------------------
// bf16 NT GEMM via mma.sync: C[m,n] = sum_k' A[m,k']*B[n,k'], logical K'=3072.
// CTA 128x256, BK=64, 4-stage cp.async pipeline, ONE barrier per chunk,
// loads for chunk c+3 issued BEFORE compute of chunk c (full overlap).
// 8 warps: 2(m) x 4(n), warp tile 64x64. blockIdx.z -> (x,w_ih)/(h,w_hh).
// ---------------------------------------------------------------------------
#define BM 128
#define BN 256
#define NCHUNK 48                     // 3072 / 64
#define A_BYTES (BM * 128)            // 16 KB
#define B_BYTES (BN * 128)            // 32 KB
#define STAGE_BYTES (A_BYTES + B_BYTES)
#define NSTAGE 4
#define SMEM_DYN (NSTAGE * STAGE_BYTES + 1024)   // 193 KB

// logical chunk -> physical chunk in [hi|lo] storage
__device__ __forceinline__ int map_a_chunk(int c) { return (c < 16) ? c : c - 16; }  // hi,hi,lo
__device__ __forceinline__ int map_w_chunk(int c) { return (c < 32) ? c : c - 32; }  // hi,lo,hi

__device__ __forceinline__ void load_chunk(uint32_t aBase, uint32_t bBase,
                                           const char* Ag, const char* Bg,
                                           int m0, int n0, int ca, int cb, int tid)
{
#pragma unroll
    for (int i = 0; i < 4; i++) {                 // A: 128 rows x 8 segs = 1024
        int idx = tid + i * 256;
        int row = idx >> 3;
        int seg = idx & 7;
        uint32_t soff = sw128((uint32_t)(row * 128 + seg * 16));
        cp_async16(aBase + soff, Ag + (size_t)(m0 + row) * 4096 + ca * 128 + seg * 16);
    }
#pragma unroll
    for (int i = 0; i < 8; i++) {                 // B: 256 rows x 8 segs = 2048
        int idx = tid + i * 256;
        int row = idx >> 3;
        int seg = idx & 7;
        uint32_t soff = sw128((uint32_t)(row * 128 + seg * 16));
        cp_async16(bBase + soff, Bg + (size_t)(n0 + row) * 4096 + cb * 128 + seg * 16);
    }
}

__global__ __launch_bounds__(256, 1) void gemm_mma_kernel()
{
    extern __shared__ char dynsmem[];

    const int tid  = threadIdx.x;
    const int wid  = tid >> 5;
    const int lane = tid & 31;
    const int z  = blockIdx.z;
    const int m0 = blockIdx.y * BM;
    const int n0 = blockIdx.x * BN;

    const char* Ag = (const char*)(g_A2 + (size_t)z * 4096 * 2048);
    const char* Bg = (const char*)(g_W2 + (size_t)z * 4096 * 2048);
    float* C = g_pre + (size_t)z * 4096 * 4096;

    const int warp_m = wid & 1;
    const int warp_n = wid >> 1;

    uint32_t base = (smem_u32(dynsmem) + 1023u) & ~1023u;

    // per-lane ldmatrix address components (within tile, pre-swizzle)
    const int ar = warp_m * 64 + (lane & 7) + (((lane >> 3) & 1) << 3);
    const int ah = (lane >> 4) & 1;
    const int br = warp_n * 64 + (lane & 7) + (((lane >> 4) & 1) << 3);
    const int bh = (lane >> 3) & 1;

    float acc[4][8][4];
#pragma unroll
    for (int mi = 0; mi < 4; mi++)
#pragma unroll
        for (int oc = 0; oc < 8; oc++)
#pragma unroll
            for (int q = 0; q < 4; q++) acc[mi][oc][q] = 0.0f;

    // prologue: stages 0..2 <- chunks 0..2 (identity mapping for c<16)
#pragma unroll
    for (int s = 0; s < 3; s++) {
        load_chunk(base + s * STAGE_BYTES, base + s * STAGE_BYTES + A_BYTES,
                   Ag, Bg, m0, n0, s, s, tid);
        CP_COMMIT();
    }

    for (int c = 0; c < NCHUNK; c++) {
        const uint32_t stg = base + (uint32_t)(c & 3) * STAGE_BYTES;
        const uint32_t aB = stg;
        const uint32_t bB = stg + A_BYTES;

        CP_WAIT2();                    // chunk c's group complete
        __syncthreads();               // all warps past chunk c-1 reads

        // refill stage (c+3)&3 = (c-1)&3 (free after the barrier), overlapping MMA
        if (c + 3 < NCHUNK) {
            int cn_ = c + 3;
            load_chunk(base + (uint32_t)(cn_ & 3) * STAGE_BYTES,
                       base + (uint32_t)(cn_ & 3) * STAGE_BYTES + A_BYTES,
                       Ag, Bg, m0, n0, map_a_chunk(cn_), map_w_chunk(cn_), tid);
        }
        CP_COMMIT();                   // always commit: uniform group accounting

#pragma unroll
        for (int ks = 0; ks < 4; ks++) {
            uint32_t a[4][4], b[4][4];
#pragma unroll
            for (int mi = 0; mi < 4; mi++) {
                uint32_t off = (uint32_t)((ar + mi * 16) * 128 + ks * 32 + ah * 16);
                ldsm_x4(a[mi][0], a[mi][1], a[mi][2], a[mi][3], aB + sw128(off));
            }
#pragma unroll
            for (int pi = 0; pi < 4; pi++) {
                uint32_t off = (uint32_t)((br + pi * 16) * 128 + ks * 32 + bh * 16);
                ldsm_x4(b[pi][0], b[pi][1], b[pi][2], b[pi][3], bB + sw128(off));
            }
#pragma unroll
            for (int mi = 0; mi < 4; mi++)
#pragma unroll
                for (int oc = 0; oc < 8; oc++) {
                    uint32_t b0 = b[oc >> 1][(oc & 1) * 2];
                    uint32_t b1 = b[oc >> 1][(oc & 1) * 2 + 1];
                    mma_bf16(acc[mi][oc][0], acc[mi][oc][1], acc[mi][oc][2], acc[mi][oc][3],
                             a[mi][0], a[mi][1], a[mi][2], a[mi][3], b0, b1);
                }
        }
    }

    // epilogue: direct fp32 stores (quad-contiguous float2 -> full 32B sectors)
    const int rbase = m0 + warp_m * 64 + (lane >> 2);
    const int cbase = n0 + warp_n * 64 + (lane & 3) * 2;
#pragma unroll
    for (int mi = 0; mi < 4; mi++) {
#pragma unroll
        for (int oc = 0; oc < 8; oc++) {
            size_t r0 = (size_t)(rbase + mi * 16) * 4096 + cbase + oc * 8;
            size_t r1 = (size_t)(rbase + mi * 16 + 8) * 4096 + cbase + oc * 8;
            *(float2*)&C[r0] = make_float2(acc[mi][oc][0], acc[mi][oc][1]);
            *(float2*)&C[r1] = make_float2(acc[mi][oc][2], acc[mi][oc][3]);
        }
    }
}

// ---------------------------------------------------------------------------
// block reductions (256 threads), single __syncthreads each
// ---------------------------------------------------------------------------
__device__ __forceinline__ void blockReduce16(float* v)   // v[16], result in all threads
{
    __shared__ float sb16[8][16];
    const unsigned m = 0xffffffffu;
#pragma unroll
    for (int o = 16; o > 0; o >>= 1)
#pragma unroll
        for (int k = 0; k < 16; k++) v[k] += __shfl_down_sync(m, v[k], o);
    int lane = threadIdx.x & 31, warp = threadIdx.x >> 5;
    if (lane == 0)
#pragma unroll
        for (int k = 0; k < 16; k++) sb16[warp][k] = v[k];
    __syncthreads();
#pragma unroll
    for (int k = 0; k < 16; k++) {
        float s = 0.f;
#pragma unroll
        for (int w = 0; w < 8; w++) s += sb16[w][k];
        v[k] = s;
    }
}

__device__ __forceinline__ float2 blockReduce2(float2 v)
{
    __shared__ float sb2[8][2];
    const unsigned m = 0xffffffffu;
#pragma unroll
    for (int o = 16; o > 0; o >>= 1) {
        v.x += __shfl_down_sync(m, v.x, o);
        v.y += __shfl_down_sync(m, v.y, o);
    }
    int lane = threadIdx.x & 31, warp = threadIdx.x >> 5;
    __syncthreads();       // protect sb2 region vs earlier sb16 readers? (distinct arrays; protects re-entry ordering)
    if (lane == 0) { sb2[warp][0] = v.x; sb2[warp][1] = v.y; }
    __syncthreads();
    float2 r = make_float2(0.f, 0.f);
#pragma unroll
    for (int w = 0; w < 8; w++) { r.x += sb2[w][0]; r.y += sb2[w][1]; }
    return r;
}

__device__ __forceinline__ float sigf(float x) { return 1.0f / (1.0f + expf(-x)); }

// ---------------------------------------------------------------------------
// Fused LN + gates + cell update. One CTA (256 thr) per batch row.
// Single fused 16-float reduction for all 4 gate LN-stat pairs.
// ---------------------------------------------------------------------------
__global__ __launch_bounds__(256) void lstm_epi_kernel(
    const float* __restrict__ cin, const float* __restrict__ b_ih,
    const float* __restrict__ gamma, const float* __restrict__ beta,
    float* __restrict__ out)
{
    const int H = 1024, B = 4096;
    const int b = blockIdx.x;
    const int j = threadIdx.x * 4;
    const float invH = 1.0f / (float)H;

    const float* pih = g_pre + (size_t)b * 4096;
    const float* phh = g_pre + (size_t)4096 * 4096 + (size_t)b * 4096;

    float vi[4][4], vh[4][4];
    float part[16];

#pragma unroll
    for (int g = 0; g < 4; g++) {
        float4 ti = *(const float4*)&pih[g * H + j];
        float4 th = *(const float4*)&phh[g * H + j];
        vi[g][0] = ti.x; vi[g][1] = ti.y; vi[g][2] = ti.z; vi[g][3] = ti.w;
        vh[g][0] = th.x; vh[g][1] = th.y; vh[g][2] = th.z; vh[g][3] = th.w;
        part[g * 4 + 0] = vi[g][0] + vi[g][1] + vi[g][2] + vi[g][3];
        part[g * 4 + 1] = vi[g][0]*vi[g][0] + vi[g][1]*vi[g][1] + vi[g][2]*vi[g][2] + vi[g][3]*vi[g][3];
        part[g * 4 + 2] = vh[g][0] + vh[g][1] + vh[g][2] + vh[g][3];
        part[g * 4 + 3] = vh[g][0]*vh[g][0] + vh[g][1]*vh[g][1] + vh[g][2]*vh[g][2] + vh[g][3]*vh[g][3];
    }

    blockReduce16(part);     // one fused reduction for all 4 gates

    float gate[4][4];
#pragma unroll
    for (int g = 0; g < 4; g++) {
        float mi = part[g * 4 + 0] * invH;
        float ri = rsqrtf(part[g * 4 + 1] * invH - mi * mi + LN_EPS);
        float mh = part[g * 4 + 2] * invH;
        float rh = rsqrtf(part[g * 4 + 3] * invH - mh * mh + LN_EPS);

        float4 gi4 = *(const float4*)&gamma[(2 * g) * H + j];
        float4 bi4 = *(const float4*)&beta [(2 * g) * H + j];
        float4 gh4 = *(const float4*)&gamma[(2 * g + 1) * H + j];
        float4 bh4 = *(const float4*)&beta [(2 * g + 1) * H + j];
        float4 bb4 = *(const float4*)&b_ih [g * H + j];
        float gi[4] = { gi4.x, gi4.y, gi4.z, gi4.w };
        float bi[4] = { bi4.x, bi4.y, bi4.z, bi4.w };
        float gh[4] = { gh4.x, gh4.y, gh4.z, gh4.w };
        float bh[4] = { bh4.x, bh4.y, bh4.z, bh4.w };
        float bb[4] = { bb4.x, bb4.y, bb4.z, bb4.w };

#pragma unroll
        for (int u = 0; u < 4; u++)
            gate[g][u] = gi[u] * (vi[g][u] - mi) * ri + bi[u]
                       + gh[u] * (vh[g][u] - mh) * rh + bh[u]
                       + bb[u];
    }

    float4 cv4 = *(const float4*)&cin[(size_t)b * H + j];
    float cv[4] = { cv4.x, cv4.y, cv4.z, cv4.w };
    float cn[4];
#pragma unroll
    for (int u = 0; u < 4; u++)
        cn[u] = sigf(gate[1][u]) * cv[u] + sigf(gate[0][u]) * tanhf(gate[2][u]);

    float2 pc;
    pc.x = cn[0] + cn[1] + cn[2] + cn[3];
    pc.y = cn[0]*cn[0] + cn[1]*cn[1] + cn[2]*cn[2] + cn[3]*cn[3];
    float2 tc = blockReduce2(pc);
    float mc = tc.x * invH;
    float rc = rsqrtf(tc.y * invH - mc * mc + LN_EPS);

    float4 g84 = *(const float4*)&gamma[8 * H + j];
    float4 b84 = *(const float4*)&beta [8 * H + j];
    float g8[4] = { g84.x, g84.y, g84.z, g84.w };
    float b8[4] = { b84.x, b84.y, b84.z, b84.w };

    float hn[4];
#pragma unroll
    for (int u = 0; u < 4; u++) {
        float lnc = g8[u] * (cn[u] - mc) * rc + b8[u];
        hn[u] = sigf(gate[3][u]) * tanhf(lnc);
    }

    *(float4*)&out[(size_t)b * H + j] = make_float4(hn[0], hn[1], hn[2], hn[3]);
    *(float4*)&out[(size_t)B * H + (size_t)b * H + j] = make_float4(cn[0], cn[1], cn[2], cn[3]);
}

// ---------------------------------------------------------------------------
// inputs (metadata order): x, h, c, w_ih, w_hh, b_ih, ln_gamma, ln_beta, time
// ---------------------------------------------------------------------------
extern "C" void kernel_launch(void* const* d_in, const int* in_sizes, int n_in,
                              void* d_out, int out_size)
{
    const float* x     = (const float*)d_in[0];
    const float* h     = (const float*)d_in[1];
    const float* c     = (const float*)d_in[2];
    const float* w_ih  = (const float*)d_in[3];
    const float* w_hh  = (const float*)d_in[4];
    const float* b_ih  = (const float*)d_in[5];
    const float* gamma = (const float*)d_in[6];
    const float* beta  = (const float*)d_in[7];
    float* out = (float*)d_out;

    cudaFuncSetAttribute(gemm_mma_kernel,
                         cudaFuncAttributeMaxDynamicSharedMemorySize, SMEM_DYN);

    split_bf16_kernel<<<dim3(4096, 1, 4), 256>>>(x, h, w_ih, w_hh);
    gemm_mma_kernel<<<dim3(16, 32, 2), 256, SMEM_DYN>>>();
    lstm_epi_kernel<<<4096, 256>>>(c, b_ih, gamma, beta, out);
}

// round 15
// speedup vs baseline: 2.7750x; 1.0117x over previous
#include <cuda_runtime.h>
#include <cuda_bf16.h>
#include <stdint.h>
#include <math.h>

#define LN_EPS 1e-5f

// ---------------------------------------------------------------------------
// Device scratch (static __device__ globals: allocation-guard safe)
// Physical layout for A2/W2: [hi(1024) | lo(1024)] per row -> 2048 bf16 cols.
// ---------------------------------------------------------------------------
__device__ __align__(1024) float g_pre[2ull * 4096 * 4096];                 // 128 MB
__device__ __align__(1024) __nv_bfloat16 g_A2[2ull * 4096 * 2048];          // 32 MB (x,h split)
__device__ __align__(1024) __nv_bfloat16 g_W2[2ull * 4096 * 2048];          // 32 MB (w_ih,w_hh split)

// ---------------------------------------------------------------------------
// helpers
// ---------------------------------------------------------------------------
__device__ __forceinline__ uint32_t smem_u32(const void* p) {
    uint32_t a;
    asm("{ .reg .u64 t; cvta.to.shared.u64 t, %1; cvt.u32.u64 %0, t; }" : "=r"(a) : "l"(p));
    return a;
}
__device__ __forceinline__ void cp_async16(uint32_t dst, const void* src) {
    asm volatile("cp.async.cg.shared.global [%0], [%1], 16;\n" :: "r"(dst), "l"(src));
}
#define CP_COMMIT() asm volatile("cp.async.commit_group;\n" ::: "memory")
#define CP_WAIT0()  asm volatile("cp.async.wait_group 0;\n" ::: "memory")

__device__ __forceinline__ uint32_t sw128(uint32_t off) { return off ^ ((off >> 3) & 0x70); }

__device__ __forceinline__ void ldsm_x4(uint32_t& r0, uint32_t& r1, uint32_t& r2, uint32_t& r3,
                                        uint32_t addr) {
    asm volatile("ldmatrix.sync.aligned.m8n8.x4.shared.b16 {%0,%1,%2,%3}, [%4];"
                 : "=r"(r0), "=r"(r1), "=r"(r2), "=r"(r3) : "r"(addr));
}
__device__ __forceinline__ void mma_bf16(float& c0, float& c1, float& c2, float& c3,
                                         uint32_t a0, uint32_t a1, uint32_t a2, uint32_t a3,
                                         uint32_t b0, uint32_t b1) {
    asm volatile("mma.sync.aligned.m16n8k16.row.col.f32.bf16.bf16.f32 "
                 "{%0,%1,%2,%3}, {%4,%5,%6,%7}, {%8,%9}, {%0,%1,%2,%3};"
                 : "+f"(c0), "+f"(c1), "+f"(c2), "+f"(c3)
                 : "r"(a0), "r"(a1), "r"(a2), "r"(a3), "r"(b0), "r"(b1));
}

// ---------------------------------------------------------------------------
// Split fp32 -> (hi, lo) bf16, physical layout [hi | lo] (2048 cols).
// Logical K'=3072 GEMM reads: A pattern [hi|hi|lo], W pattern [hi|lo|hi]
// via chunk remapping in load_chunk. sum = Ahi*Whi + Ahi*Wlo + Alo*Whi.
// ---------------------------------------------------------------------------
__global__ __launch_bounds__(256) void split_bf16_kernel(
    const float* __restrict__ x, const float* __restrict__ h,
    const float* __restrict__ wih, const float* __restrict__ whh)
{
    int z = blockIdx.z;
    const float* src = (z == 0) ? x : (z == 1) ? h : (z == 2) ? wih : whh;
    __nv_bfloat16* dst = (z < 2) ? (g_A2 + (size_t)z * 4096 * 2048)
                                 : (g_W2 + (size_t)(z - 2) * 4096 * 2048);
    int idx = blockIdx.x * 256 + threadIdx.x;
    int row = idx >> 8;
    int col = (idx & 255) * 4;
    float4 v = *(const float4*)&src[(size_t)row * 1024 + col];
    float vv[4] = { v.x, v.y, v.z, v.w };
    unsigned short hs[4], ls[4];
#pragma unroll
    for (int u = 0; u < 4; u++) {
        __nv_bfloat16 hb = __float2bfloat16(vv[u]);
        __nv_bfloat16 lb = __float2bfloat16(vv[u] - __bfloat162float(hb));
        hs[u] = __bfloat16_as_ushort(hb);
        ls[u] = __bfloat16_as_ushort(lb);
    }
    uint2 hv = make_uint2((uint32_t)hs[0] | ((uint32_t)hs[1] << 16),
                          (uint32_t)hs[2] | ((uint32_t)hs[3] << 16));
    uint2 lv = make_uint2((uint32_t)ls[0] | ((uint32_t)ls[1] << 16),
                          (uint32_t)ls[2] | ((uint32_t)ls[3] << 16));
    size_t rb = (size_t)row * 2048;
    *(uint2*)&dst[rb + col]        = hv;
    *(uint2*)&dst[rb + 1024 + col] = lv;
}

// ---------------------------------------------------------------------------
// bf16 NT GEMM via mma.sync: C[m,n] = sum_k' A[m,k']*B[n,k'], logical K'=3072.
// CTA 128x256, BK=64, 4-stage smem, CHUNK-PAIR pipeline:
//   one wait_group + one __syncthreads per 2 chunks; refill of chunks c+2,c+3
//   (into the stages freed last iteration) issued before the 8-ks compute.
// 8 warps: 2(m) x 4(n), warp tile 64x64. blockIdx.z -> (x,w_ih)/(h,w_hh).
// ---------------------------------------------------------------------------
#define BM 128
#define BN 256
#define NCHUNK 48                     // 3072 / 64
#define A_BYTES (BM * 128)            // 16 KB
#define B_BYTES (BN * 128)            // 32 KB
#define STAGE_BYTES (A_BYTES + B_BYTES)
#define NSTAGE 4
#define SMEM_DYN (NSTAGE * STAGE_BYTES + 1024)   // 193 KB

// logical chunk -> physical chunk in [hi|lo] storage
__device__ __forceinline__ int map_a_chunk(int c) { return (c < 16) ? c : c - 16; }  // hi,hi,lo
__device__ __forceinline__ int map_w_chunk(int c) { return (c < 32) ? c : c - 32; }  // hi,lo,hi

__device__ __forceinline__ void load_chunk(uint32_t aBase, uint32_t bBase,
                                           const char* Ag, const char* Bg,
                                           int m0, int n0, int ca, int cb, int tid)
{
#pragma unroll
    for (int i = 0; i < 4; i++) {                 // A: 128 rows x 8 segs = 1024
        int idx = tid + i * 256;
        int row = idx >> 3;
        int seg = idx & 7;
        uint32_t soff = sw128((uint32_t)(row * 128 + seg * 16));
        cp_async16(aBase + soff, Ag + (size_t)(m0 + row) * 4096 + ca * 128 + seg * 16);
    }
#pragma unroll
    for (int i = 0; i < 8; i++) {                 // B: 256 rows x 8 segs = 2048
        int idx = tid + i * 256;
        int row = idx >> 3;
        int seg = idx & 7;
        uint32_t soff = sw128((uint32_t)(row * 128 + seg * 16));
        cp_async16(bBase + soff, Bg + (size_t)(n0 + row) * 4096 + cb * 128 + seg * 16);
    }
}

__global__ __launch_bounds__(256, 1) void gemm_mma_kernel()
{
    extern __shared__ char dynsmem[];

    const int tid  = threadIdx.x;
    const int wid  = tid >> 5;
    const int lane = tid & 31;
    const int z  = blockIdx.z;
    const int m0 = blockIdx.y * BM;
    const int n0 = blockIdx.x * BN;

    const char* Ag = (const char*)(g_A2 + (size_t)z * 4096 * 2048);
    const char* Bg = (const char*)(g_W2 + (size_t)z * 4096 * 2048);
    float* C = g_pre + (size_t)z * 4096 * 4096;

    const int warp_m = wid & 1;
    const int warp_n = wid >> 1;

    uint32_t base = (smem_u32(dynsmem) + 1023u) & ~1023u;

    // per-lane ldmatrix address components (within tile, pre-swizzle)
    const int ar = warp_m * 64 + (lane & 7) + (((lane >> 3) & 1) << 3);
    const int ah = (lane >> 4) & 1;
    const int br = warp_n * 64 + (lane & 7) + (((lane >> 4) & 1) << 3);
    const int bh = (lane >> 3) & 1;

    float acc[4][8][4];
#pragma unroll
    for (int mi = 0; mi < 4; mi++)
#pragma unroll
        for (int oc = 0; oc < 8; oc++)
#pragma unroll
            for (int q = 0; q < 4; q++) acc[mi][oc][q] = 0.0f;

    // prologue: chunks 0,1 into stages 0,1 (identity mapping for c<16)
    load_chunk(base,               base + A_BYTES,               Ag, Bg, m0, n0, 0, 0, tid);
    load_chunk(base + STAGE_BYTES, base + STAGE_BYTES + A_BYTES, Ag, Bg, m0, n0, 1, 1, tid);
    CP_COMMIT();

    for (int c = 0; c < NCHUNK; c += 2) {
        CP_WAIT0();                    // chunks c, c+1 landed (issued last iter)
        __syncthreads();               // all warps done reading chunks c-2, c-1

        // refill the two stages freed last iteration with chunks c+2, c+3;
        // issued BEFORE compute so LSU overlaps the 8-ks MMA block
        if (c + 2 < NCHUNK) {
            int c2 = c + 2, c3 = c + 3;
            load_chunk(base + (uint32_t)(c2 & 3) * STAGE_BYTES,
                       base + (uint32_t)(c2 & 3) * STAGE_BYTES + A_BYTES,
                       Ag, Bg, m0, n0, map_a_chunk(c2), map_w_chunk(c2), tid);
            load_chunk(base + (uint32_t)(c3 & 3) * STAGE_BYTES,
                       base + (uint32_t)(c3 & 3) * STAGE_BYTES + A_BYTES,
                       Ag, Bg, m0, n0, map_a_chunk(c3), map_w_chunk(c3), tid);
            CP_COMMIT();
        }

        // compute chunks c and c+1: 8 straight-line ks steps, no barriers
#pragma unroll
        for (int half = 0; half < 2; half++) {
            const uint32_t stg = base + (uint32_t)((c + half) & 3) * STAGE_BYTES;
            const uint32_t aB = stg;
            const uint32_t bB = stg + A_BYTES;
#pragma unroll
            for (int ks = 0; ks < 4; ks++) {
                uint32_t a[4][4], b[4][4];
#pragma unroll
                for (int mi = 0; mi < 4; mi++) {
                    uint32_t off = (uint32_t)((ar + mi * 16) * 128 + ks * 32 + ah * 16);
                    ldsm_x4(a[mi][0], a[mi][1], a[mi][2], a[mi][3], aB + sw128(off));
                }
#pragma unroll
                for (int pi = 0; pi < 4; pi++) {
                    uint32_t off = (uint32_t)((br + pi * 16) * 128 + ks * 32 + bh * 16);
                    ldsm_x4(b[pi][0], b[pi][1], b[pi][2], b[pi][3], bB + sw128(off));
                }
#pragma unroll
                for (int mi = 0; mi < 4; mi++)
#pragma unroll
                    for (int oc = 0; oc < 8; oc++) {
                        uint32_t b0 = b[oc >> 1][(oc & 1) * 2];
                        uint32_t b1 = b[oc >> 1][(oc & 1) * 2 + 1];
                        mma_bf16(acc[mi][oc][0], acc[mi][oc][1], acc[mi][oc][2], acc[mi][oc][3],
                                 a[mi][0], a[mi][1], a[mi][2], a[mi][3], b0, b1);
                    }
            }
        }
    }

    // epilogue: streaming fp32 stores (evict-first: g_pre not reused before epi;
    // keeps L2 resident for A2/W2 chunk reuse)
    const int rbase = m0 + warp_m * 64 + (lane >> 2);
    const int cbase = n0 + warp_n * 64 + (lane & 3) * 2;
#pragma unroll
    for (int mi = 0; mi < 4; mi++) {
#pragma unroll
        for (int oc = 0; oc < 8; oc++) {
            size_t r0 = (size_t)(rbase + mi * 16) * 4096 + cbase + oc * 8;
            size_t r1 = (size_t)(rbase + mi * 16 + 8) * 4096 + cbase + oc * 8;
            __stcs((float2*)&C[r0], make_float2(acc[mi][oc][0], acc[mi][oc][1]));
            __stcs((float2*)&C[r1], make_float2(acc[mi][oc][2], acc[mi][oc][3]));
        }
    }
}

// ---------------------------------------------------------------------------
// block reductions (256 threads), single __syncthreads each
// ---------------------------------------------------------------------------
__device__ __forceinline__ void blockReduce16(float* v)   // v[16], result in all threads
{
    __shared__ float sb16[8][16];
    const unsigned m = 0xffffffffu;
#pragma unroll
    for (int o = 16; o > 0; o >>= 1)
#pragma unroll
        for (int k = 0; k < 16; k++) v[k] += __shfl_down_sync(m, v[k], o);
    int lane = threadIdx.x & 31, warp = threadIdx.x >> 5;
    if (lane == 0)
#pragma unroll
        for (int k = 0; k < 16; k++) sb16[warp][k] = v[k];
    __syncthreads();
#pragma unroll
    for (int k = 0; k < 16; k++) {
        float s = 0.f;
#pragma unroll
        for (int w = 0; w < 8; w++) s += sb16[w][k];
        v[k] = s;
    }
}

__device__ __forceinline__ float2 blockReduce2(float2 v)
{
    __shared__ float sb2[8][2];
    const unsigned m = 0xffffffffu;
#pragma unroll
    for (int o = 16; o > 0; o >>= 1) {
        v.x += __shfl_down_sync(m, v.x, o);
        v.y += __shfl_down_sync(m, v.y, o);
    }
    int lane = threadIdx.x & 31, warp = threadIdx.x >> 5;
    __syncthreads();
    if (lane == 0) { sb2[warp][0] = v.x; sb2[warp][1] = v.y; }
    __syncthreads();
    float2 r = make_float2(0.f, 0.f);
#pragma unroll
    for (int w = 0; w < 8; w++) { r.x += sb2[w][0]; r.y += sb2[w][1]; }
    return r;
}

__device__ __forceinline__ float sigf(float x) { return 1.0f / (1.0f + expf(-x)); }

// ---------------------------------------------------------------------------
// Fused LN + gates + cell update. One CTA (256 thr) per batch row.
// Single fused 16-float reduction for all 4 gate LN-stat pairs.
// ---------------------------------------------------------------------------
__global__ __launch_bounds__(256) void lstm_epi_kernel(
    const float* __restrict__ cin, const float* __restrict__ b_ih,
    const float* __restrict__ gamma, const float* __restrict__ beta,
    float* __restrict__ out)
{
    const int H = 1024, B = 4096;
    const int b = blockIdx.x;
    const int j = threadIdx.x * 4;
    const float invH = 1.0f / (float)H;

    const float* pih = g_pre + (size_t)b * 4096;
    const float* phh = g_pre + (size_t)4096 * 4096 + (size_t)b * 4096;

    float vi[4][4], vh[4][4];
    float part[16];

#pragma unroll
    for (int g = 0; g < 4; g++) {
        float4 ti = __ldcs((const float4*)&pih[g * H + j]);   // streaming: no reuse
        float4 th = __ldcs((const float4*)&phh[g * H + j]);
        vi[g][0] = ti.x; vi[g][1] = ti.y; vi[g][2] = ti.z; vi[g][3] = ti.w;
        vh[g][0] = th.x; vh[g][1] = th.y; vh[g][2] = th.z; vh[g][3] = th.w;
        part[g * 4 + 0] = vi[g][0] + vi[g][1] + vi[g][2] + vi[g][3];
        part[g * 4 + 1] = vi[g][0]*vi[g][0] + vi[g][1]*vi[g][1] + vi[g][2]*vi[g][2] + vi[g][3]*vi[g][3];
        part[g * 4 + 2] = vh[g][0] + vh[g][1] + vh[g][2] + vh[g][3];
        part[g * 4 + 3] = vh[g][0]*vh[g][0] + vh[g][1]*vh[g][1] + vh[g][2]*vh[g][2] + vh[g][3]*vh[g][3];
    }

    blockReduce16(part);     // one fused reduction for all 4 gates

    float gate[4][4];
#pragma unroll
    for (int g = 0; g < 4; g++) {
        float mi = part[g * 4 + 0] * invH;
        float ri = rsqrtf(part[g * 4 + 1] * invH - mi * mi + LN_EPS);
        float mh = part[g * 4 + 2] * invH;
        float rh = rsqrtf(part[g * 4 + 3] * invH - mh * mh + LN_EPS);

        float4 gi4 = *(const float4*)&gamma[(2 * g) * H + j];
        float4 bi4 = *(const float4*)&beta [(2 * g) * H + j];
        float4 gh4 = *(const float4*)&gamma[(2 * g + 1) * H + j];
        float4 bh4 = *(const float4*)&beta [(2 * g + 1) * H + j];
        float4 bb4 = *(const float4*)&b_ih [g * H + j];
        float gi[4] = { gi4.x, gi4.y, gi4.z, gi4.w };
        float bi[4] = { bi4.x, bi4.y, bi4.z, bi4.w };
        float gh[4] = { gh4.x, gh4.y, gh4.z, gh4.w };
        float bh[4] = { bh4.x, bh4.y, bh4.z, bh4.w };
        float bb[4] = { bb4.x, bb4.y, bb4.z, bb4.w };

#pragma unroll
        for (int u = 0; u < 4; u++)
            gate[g][u] = gi[u] * (vi[g][u] - mi) * ri + bi[u]
                       + gh[u] * (vh[g][u] - mh) * rh + bh[u]
                       + bb[u];
    }

    float4 cv4 = *(const float4*)&cin[(size_t)b * H + j];
    float cv[4] = { cv4.x, cv4.y, cv4.z, cv4.w };
    float cn[4];
#pragma unroll
    for (int u = 0; u < 4; u++)
        cn[u] = sigf(gate[1][u]) * cv[u] + sigf(gate[0][u]) * tanhf(gate[2][u]);

    float2 pc;
    pc.x = cn[0] + cn[1] + cn[2] + cn[3];
    pc.y = cn[0]*cn[0] + cn[1]*cn[1] + cn[2]*cn[2] + cn[3]*cn[3];
    float2 tc = blockReduce2(pc);
    float mc = tc.x * invH;
    float rc = rsqrtf(tc.y * invH - mc * mc + LN_EPS);

    float4 g84 = *(const float4*)&gamma[8 * H + j];
    float4 b84 = *(const float4*)&beta [8 * H + j];
    float g8[4] = { g84.x, g84.y, g84.z, g84.w };
    float b8[4] = { b84.x, b84.y, b84.z, b84.w };

    float hn[4];
#pragma unroll
    for (int u = 0; u < 4; u++) {
        float lnc = g8[u] * (cn[u] - mc) * rc + b8[u];
        hn[u] = sigf(gate[3][u]) * tanhf(lnc);
    }

    *(float4*)&out[(size_t)b * H + j] = make_float4(hn[0], hn[1], hn[2], hn[3]);
    *(float4*)&out[(size_t)B * H + (size_t)b * H + j] = make_float4(cn[0], cn[1], cn[2], cn[3]);
}

// ---------------------------------------------------------------------------
// inputs (metadata order): x, h, c, w_ih, w_hh, b_ih, ln_gamma, ln_beta, time
// ---------------------------------------------------------------------------
extern "C" void kernel_launch(void* const* d_in, const int* in_sizes, int n_in,
                              void* d_out, int out_size)
{
    const float* x     = (const float*)d_in[0];
    const float* h     = (const float*)d_in[1];
    const float* c     = (const float*)d_in[2];
    const float* w_ih  = (const float*)d_in[3];
    const float* w_hh  = (const float*)d_in[4];
    const float* b_ih  = (const float*)d_in[5];
    const float* gamma = (const float*)d_in[6];
    const float* beta  = (const float*)d_in[7];
    float* out = (float*)d_out;

    cudaFuncSetAttribute(gemm_mma_kernel,
                         cudaFuncAttributeMaxDynamicSharedMemorySize, SMEM_DYN);

    split_bf16_kernel<<<dim3(4096, 1, 4), 256>>>(x, h, w_ih, w_hh);
    gemm_mma_kernel<<<dim3(16, 32, 2), 256, SMEM_DYN>>>();
    lstm_epi_kernel<<<4096, 256>>>(c, b_ih, gamma, beta, out);
}

// round 16
// speedup vs baseline: 6.1370x; 2.2116x over previous
#include <cuda_runtime.h>
#include <cuda_fp16.h>
#include <stdint.h>
#include <math.h>

#define LN_EPS 1e-5f

// ---------------------------------------------------------------------------
// Device scratch (static __device__ globals: allocation-guard safe)
// ---------------------------------------------------------------------------
__device__ __align__(1024) float  g_pre[2ull * 4096 * 4096];    // 128 MB
__device__ __align__(1024) __half g_A2[2ull * 4096 * 1024];     // 16 MB (x,h fp16)
__device__ __align__(1024) __half g_W2[2ull * 4096 * 1024];     // 16 MB (w_ih,w_hh fp16)

// ---------------------------------------------------------------------------
// helpers
// ---------------------------------------------------------------------------
__device__ __forceinline__ uint32_t smem_u32(const void* p) {
    uint32_t a;
    asm("{ .reg .u64 t; cvta.to.shared.u64 t, %1; cvt.u32.u64 %0, t; }" : "=r"(a) : "l"(p));
    return a;
}
__device__ __forceinline__ void cp_async16(uint32_t dst, const void* src) {
    asm volatile("cp.async.cg.shared.global [%0], [%1], 16;\n" :: "r"(dst), "l"(src));
}
#define CP_COMMIT() asm volatile("cp.async.commit_group;\n" ::: "memory")
#define CP_WAIT0()  asm volatile("cp.async.wait_group 0;\n" ::: "memory")

__device__ __forceinline__ uint32_t sw128(uint32_t off) { return off ^ ((off >> 3) & 0x70); }

__device__ __forceinline__ void ldsm_x4(uint32_t& r0, uint32_t& r1, uint32_t& r2, uint32_t& r3,
                                        uint32_t addr) {
    asm volatile("ldmatrix.sync.aligned.m8n8.x4.shared.b16 {%0,%1,%2,%3}, [%4];"
                 : "=r"(r0), "=r"(r1), "=r"(r2), "=r"(r3) : "r"(addr));
}
__device__ __forceinline__ void mma_f16(float& c0, float& c1, float& c2, float& c3,
                                        uint32_t a0, uint32_t a1, uint32_t a2, uint32_t a3,
                                        uint32_t b0, uint32_t b1) {
    asm volatile("mma.sync.aligned.m16n8k16.row.col.f32.f16.f16.f32 "
                 "{%0,%1,%2,%3}, {%4,%5,%6,%7}, {%8,%9}, {%0,%1,%2,%3};"
                 : "+f"(c0), "+f"(c1), "+f"(c2), "+f"(c3)
                 : "r"(a0), "r"(a1), "r"(a2), "r"(a3), "r"(b0), "r"(b1));
}

// ---------------------------------------------------------------------------
// Convert fp32 -> fp16 (single-term; mma accumulates in exact fp32)
// ---------------------------------------------------------------------------
__global__ __launch_bounds__(256) void conv_f16_kernel(
    const float* __restrict__ x, const float* __restrict__ h,
    const float* __restrict__ wih, const float* __restrict__ whh)
{
    int z = blockIdx.z;
    const float* src = (z == 0) ? x : (z == 1) ? h : (z == 2) ? wih : whh;
    __half* dst = (z < 2) ? (g_A2 + (size_t)z * 4096 * 1024)
                          : (g_W2 + (size_t)(z - 2) * 4096 * 1024);
    size_t idx = (size_t)blockIdx.x * 256 + threadIdx.x;      // float4 index
    float4 v = *(const float4*)&src[idx * 4];
    __half2 p0 = __floats2half2_rn(v.x, v.y);
    __half2 p1 = __floats2half2_rn(v.z, v.w);
    uint2 pv = make_uint2(*(uint32_t*)&p0, *(uint32_t*)&p1);
    *(uint2*)&dst[idx * 4] = pv;
}

// ---------------------------------------------------------------------------
// fp16 NT GEMM via mma.sync: C[m,n] = sum_k A[m,k]*B[n,k], M=N=4096, K=1024.
// CTA 128x256, BK=64, 4-stage smem, chunk-pair pipeline (one sync / 2 chunks).
// 8 warps: 2(m) x 4(n), warp tile 64x64. blockIdx.z -> (x,w_ih)/(h,w_hh).
// ---------------------------------------------------------------------------
#define BM 128
#define BN 256
#define NCHUNK 16                     // 1024 / 64
#define ROW_BYTES 2048                // 1024 fp16 per row
#define A_BYTES (BM * 128)            // 16 KB
#define B_BYTES (BN * 128)            // 32 KB
#define STAGE_BYTES (A_BYTES + B_BYTES)
#define NSTAGE 4
#define SMEM_DYN (NSTAGE * STAGE_BYTES + 1024)   // 193 KB

__device__ __forceinline__ void load_chunk(uint32_t aBase, uint32_t bBase,
                                           const char* Ag, const char* Bg,
                                           int m0, int n0, int kc, int tid)
{
#pragma unroll
    for (int i = 0; i < 4; i++) {                 // A: 128 rows x 8 segs = 1024
        int idx = tid + i * 256;
        int row = idx >> 3;
        int seg = idx & 7;
        uint32_t soff = sw128((uint32_t)(row * 128 + seg * 16));
        cp_async16(aBase + soff, Ag + (size_t)(m0 + row) * ROW_BYTES + kc * 128 + seg * 16);
    }
#pragma unroll
    for (int i = 0; i < 8; i++) {                 // B: 256 rows x 8 segs = 2048
        int idx = tid + i * 256;
        int row = idx >> 3;
        int seg = idx & 7;
        uint32_t soff = sw128((uint32_t)(row * 128 + seg * 16));
        cp_async16(bBase + soff, Bg + (size_t)(n0 + row) * ROW_BYTES + kc * 128 + seg * 16);
    }
}

__global__ __launch_bounds__(256, 1) void gemm_mma_kernel()
{
    extern __shared__ char dynsmem[];

    const int tid  = threadIdx.x;
    const int wid  = tid >> 5;
    const int lane = tid & 31;
    const int z  = blockIdx.z;
    const int m0 = blockIdx.y * BM;
    const int n0 = blockIdx.x * BN;

    const char* Ag = (const char*)(g_A2 + (size_t)z * 4096 * 1024);
    const char* Bg = (const char*)(g_W2 + (size_t)z * 4096 * 1024);
    float* C = g_pre + (size_t)z * 4096 * 4096;

    const int warp_m = wid & 1;
    const int warp_n = wid >> 1;

    uint32_t base = (smem_u32(dynsmem) + 1023u) & ~1023u;

    // per-lane ldmatrix address components (within tile, pre-swizzle)
    const int ar = warp_m * 64 + (lane & 7) + (((lane >> 3) & 1) << 3);
    const int ah = (lane >> 4) & 1;
    const int br = warp_n * 64 + (lane & 7) + (((lane >> 4) & 1) << 3);
    const int bh = (lane >> 3) & 1;

    float acc[4][8][4];
#pragma unroll
    for (int mi = 0; mi < 4; mi++)
#pragma unroll
        for (int oc = 0; oc < 8; oc++)
#pragma unroll
            for (int q = 0; q < 4; q++) acc[mi][oc][q] = 0.0f;

    // prologue: chunks 0,1 into stages 0,1
    load_chunk(base,               base + A_BYTES,               Ag, Bg, m0, n0, 0, tid);
    load_chunk(base + STAGE_BYTES, base + STAGE_BYTES + A_BYTES, Ag, Bg, m0, n0, 1, tid);
    CP_COMMIT();

    for (int c = 0; c < NCHUNK; c += 2) {
        CP_WAIT0();                    // chunks c, c+1 landed
        __syncthreads();               // all warps done reading chunks c-2, c-1

        // refill freed stages with chunks c+2, c+3; overlaps the 8-ks compute
        if (c + 2 < NCHUNK) {
            load_chunk(base + (uint32_t)((c + 2) & 3) * STAGE_BYTES,
                       base + (uint32_t)((c + 2) & 3) * STAGE_BYTES + A_BYTES,
                       Ag, Bg, m0, n0, c + 2, tid);
            load_chunk(base + (uint32_t)((c + 3) & 3) * STAGE_BYTES,
                       base + (uint32_t)((c + 3) & 3) * STAGE_BYTES + A_BYTES,
                       Ag, Bg, m0, n0, c + 3, tid);
            CP_COMMIT();
        }

        // compute chunks c and c+1: 8 straight-line ks steps, no barriers
#pragma unroll
        for (int half = 0; half < 2; half++) {
            const uint32_t stg = base + (uint32_t)((c + half) & 3) * STAGE_BYTES;
            const uint32_t aB = stg;
            const uint32_t bB = stg + A_BYTES;
#pragma unroll
            for (int ks = 0; ks < 4; ks++) {
                uint32_t a[4][4], b[4][4];
#pragma unroll
                for (int mi = 0; mi < 4; mi++) {
                    uint32_t off = (uint32_t)((ar + mi * 16) * 128 + ks * 32 + ah * 16);
                    ldsm_x4(a[mi][0], a[mi][1], a[mi][2], a[mi][3], aB + sw128(off));
                }
#pragma unroll
                for (int pi = 0; pi < 4; pi++) {
                    uint32_t off = (uint32_t)((br + pi * 16) * 128 + ks * 32 + bh * 16);
                    ldsm_x4(b[pi][0], b[pi][1], b[pi][2], b[pi][3], bB + sw128(off));
                }
#pragma unroll
                for (int mi = 0; mi < 4; mi++)
#pragma unroll
                    for (int oc = 0; oc < 8; oc++) {
                        uint32_t b0 = b[oc >> 1][(oc & 1) * 2];
                        uint32_t b1 = b[oc >> 1][(oc & 1) * 2 + 1];
                        mma_f16(acc[mi][oc][0], acc[mi][oc][1], acc[mi][oc][2], acc[mi][oc][3],
                                a[mi][0], a[mi][1], a[mi][2], a[mi][3], b0, b1);
                    }
            }
        }
    }

    // epilogue: streaming fp32 stores (evict-first; g_pre read only by epi)
    const int rbase = m0 + warp_m * 64 + (lane >> 2);
    const int cbase = n0 + warp_n * 64 + (lane & 3) * 2;
#pragma unroll
    for (int mi = 0; mi < 4; mi++) {
#pragma unroll
        for (int oc = 0; oc < 8; oc++) {
            size_t r0 = (size_t)(rbase + mi * 16) * 4096 + cbase + oc * 8;
            size_t r1 = (size_t)(rbase + mi * 16 + 8) * 4096 + cbase + oc * 8;
            __stcs((float2*)&C[r0], make_float2(acc[mi][oc][0], acc[mi][oc][1]));
            __stcs((float2*)&C[r1], make_float2(acc[mi][oc][2], acc[mi][oc][3]));
        }
    }
}

// ---------------------------------------------------------------------------
// block reductions (256 threads), single __syncthreads each
// ---------------------------------------------------------------------------
__device__ __forceinline__ void blockReduce16(float* v)   // v[16], result in all threads
{
    __shared__ float sb16[8][16];
    const unsigned m = 0xffffffffu;
#pragma unroll
    for (int o = 16; o > 0; o >>= 1)
#pragma unroll
        for (int k = 0; k < 16; k++) v[k] += __shfl_down_sync(m, v[k], o);
    int lane = threadIdx.x & 31, warp = threadIdx.x >> 5;
    if (lane == 0)
#pragma unroll
        for (int k = 0; k < 16; k++) sb16[warp][k] = v[k];
    __syncthreads();
#pragma unroll
    for (int k = 0; k < 16; k++) {
        float s = 0.f;
#pragma unroll
        for (int w = 0; w < 8; w++) s += sb16[w][k];
        v[k] = s;
    }
}

__device__ __forceinline__ float2 blockReduce2(float2 v)
{
    __shared__ float sb2[8][2];
    const unsigned m = 0xffffffffu;
#pragma unroll
    for (int o = 16; o > 0; o >>= 1) {
        v.x += __shfl_down_sync(m, v.x, o);
        v.y += __shfl_down_sync(m, v.y, o);
    }
    int lane = threadIdx.x & 31, warp = threadIdx.x >> 5;
    __syncthreads();
    if (lane == 0) { sb2[warp][0] = v.x; sb2[warp][1] = v.y; }
    __syncthreads();
    float2 r = make_float2(0.f, 0.f);
#pragma unroll
    for (int w = 0; w < 8; w++) { r.x += sb2[w][0]; r.y += sb2[w][1]; }
    return r;
}

__device__ __forceinline__ float sigf(float x) { return 1.0f / (1.0f + expf(-x)); }

// ---------------------------------------------------------------------------
// Fused LN + gates + cell update. One CTA (256 thr) per batch row.
// ---------------------------------------------------------------------------
__global__ __launch_bounds__(256) void lstm_epi_kernel(
    const float* __restrict__ cin, const float* __restrict__ b_ih,
    const float* __restrict__ gamma, const float* __restrict__ beta,
    float* __restrict__ out)
{
    const int H = 1024, B = 4096;
    const int b = blockIdx.x;
    const int j = threadIdx.x * 4;
    const float invH = 1.0f / (float)H;

    const float* pih = g_pre + (size_t)b * 4096;
    const float* phh = g_pre + (size_t)4096 * 4096 + (size_t)b * 4096;

    float vi[4][4], vh[4][4];
    float part[16];

#pragma unroll
    for (int g = 0; g < 4; g++) {
        float4 ti = __ldcs((const float4*)&pih[g * H + j]);
        float4 th = __ldcs((const float4*)&phh[g * H + j]);
        vi[g][0] = ti.x; vi[g][1] = ti.y; vi[g][2] = ti.z; vi[g][3] = ti.w;
        vh[g][0] = th.x; vh[g][1] = th.y; vh[g][2] = th.z; vh[g][3] = th.w;
        part[g * 4 + 0] = vi[g][0] + vi[g][1] + vi[g][2] + vi[g][3];
        part[g * 4 + 1] = vi[g][0]*vi[g][0] + vi[g][1]*vi[g][1] + vi[g][2]*vi[g][2] + vi[g][3]*vi[g][3];
        part[g * 4 + 2] = vh[g][0] + vh[g][1] + vh[g][2] + vh[g][3];
        part[g * 4 + 3] = vh[g][0]*vh[g][0] + vh[g][1]*vh[g][1] + vh[g][2]*vh[g][2] + vh[g][3]*vh[g][3];
    }

    blockReduce16(part);     // one fused reduction for all 4 gates

    float gate[4][4];
#pragma unroll
    for (int g = 0; g < 4; g++) {
        float mi = part[g * 4 + 0] * invH;
        float ri = rsqrtf(part[g * 4 + 1] * invH - mi * mi + LN_EPS);
        float mh = part[g * 4 + 2] * invH;
        float rh = rsqrtf(part[g * 4 + 3] * invH - mh * mh + LN_EPS);

        float4 gi4 = *(const float4*)&gamma[(2 * g) * H + j];
        float4 bi4 = *(const float4*)&beta [(2 * g) * H + j];
        float4 gh4 = *(const float4*)&gamma[(2 * g + 1) * H + j];
        float4 bh4 = *(const float4*)&beta [(2 * g + 1) * H + j];
        float4 bb4 = *(const float4*)&b_ih [g * H + j];
        float gi[4] = { gi4.x, gi4.y, gi4.z, gi4.w };
        float bi[4] = { bi4.x, bi4.y, bi4.z, bi4.w };
        float gh[4] = { gh4.x, gh4.y, gh4.z, gh4.w };
        float bh[4] = { bh4.x, bh4.y, bh4.z, bh4.w };
        float bb[4] = { bb4.x, bb4.y, bb4.z, bb4.w };

#pragma unroll
        for (int u = 0; u < 4; u++)
            gate[g][u] = gi[u] * (vi[g][u] - mi) * ri + bi[u]
                       + gh[u] * (vh[g][u] - mh) * rh + bh[u]
                       + bb[u];
    }

    float4 cv4 = *(const float4*)&cin[(size_t)b * H + j];
    float cv[4] = { cv4.x, cv4.y, cv4.z, cv4.w };
    float cn[4];
#pragma unroll
    for (int u = 0; u < 4; u++)
        cn[u] = sigf(gate[1][u]) * cv[u] + sigf(gate[0][u]) * tanhf(gate[2][u]);

    float2 pc;
    pc.x = cn[0] + cn[1] + cn[2] + cn[3];
    pc.y = cn[0]*cn[0] + cn[1]*cn[1] + cn[2]*cn[2] + cn[3]*cn[3];
    float2 tc = blockReduce2(pc);
    float mc = tc.x * invH;
    float rc = rsqrtf(tc.y * invH - mc * mc + LN_EPS);

    float4 g84 = *(const float4*)&gamma[8 * H + j];
    float4 b84 = *(const float4*)&beta [8 * H + j];
    float g8[4] = { g84.x, g84.y, g84.z, g84.w };
    float b8[4] = { b84.x, b84.y, b84.z, b84.w };

    float hn[4];
#pragma unroll
    for (int u = 0; u < 4; u++) {
        float lnc = g8[u] * (cn[u] - mc) * rc + b8[u];
        hn[u] = sigf(gate[3][u]) * tanhf(lnc);
    }

    *(float4*)&out[(size_t)b * H + j] = make_float4(hn[0], hn[1], hn[2], hn[3]);
    *(float4*)&out[(size_t)B * H + (size_t)b * H + j] = make_float4(cn[0], cn[1], cn[2], cn[3]);
}

// ---------------------------------------------------------------------------
// inputs (metadata order): x, h, c, w_ih, w_hh, b_ih, ln_gamma, ln_beta, time
// ---------------------------------------------------------------------------
extern "C" void kernel_launch(void* const* d_in, const int* in_sizes, int n_in,
                              void* d_out, int out_size)
{
    const float* x     = (const float*)d_in[0];
    const float* h     = (const float*)d_in[1];
    const float* c     = (const float*)d_in[2];
    const float* w_ih  = (const float*)d_in[3];
    const float* w_hh  = (const float*)d_in[4];
    const float* b_ih  = (const float*)d_in[5];
    const float* gamma = (const float*)d_in[6];
    const float* beta  = (const float*)d_in[7];
    float* out = (float*)d_out;

    cudaFuncSetAttribute(gemm_mma_kernel,
                         cudaFuncAttributeMaxDynamicSharedMemorySize, SMEM_DYN);

    conv_f16_kernel<<<dim3(4096, 1, 4), 256>>>(x, h, w_ih, w_hh);
    gemm_mma_kernel<<<dim3(16, 32, 2), 256, SMEM_DYN>>>();
    lstm_epi_kernel<<<4096, 256>>>(c, b_ih, gamma, beta, out);
}

// round 17
// speedup vs baseline: 6.3480x; 1.0344x over previous
#include <cuda_runtime.h>
#include <cuda_fp16.h>
#include <stdint.h>
#include <math.h>

#define LN_EPS 1e-5f

// ---------------------------------------------------------------------------
// Device scratch (static __device__ globals: allocation-guard safe)
// ---------------------------------------------------------------------------
__device__ __align__(1024) __half g_pre[2ull * 4096 * 4096];    // 64 MB (fp16 pre-acts)
__device__ __align__(1024) __half g_A2[2ull * 4096 * 1024];     // 16 MB (x,h fp16)
__device__ __align__(1024) __half g_W2[2ull * 4096 * 1024];     // 16 MB (w_ih,w_hh fp16)

// ---------------------------------------------------------------------------
// helpers
// ---------------------------------------------------------------------------
__device__ __forceinline__ uint32_t smem_u32(const void* p) {
    uint32_t a;
    asm("{ .reg .u64 t; cvta.to.shared.u64 t, %1; cvt.u32.u64 %0, t; }" : "=r"(a) : "l"(p));
    return a;
}
__device__ __forceinline__ void cp_async16(uint32_t dst, const void* src) {
    asm volatile("cp.async.cg.shared.global [%0], [%1], 16;\n" :: "r"(dst), "l"(src));
}
#define CP_COMMIT() asm volatile("cp.async.commit_group;\n" ::: "memory")
#define CP_WAIT0()  asm volatile("cp.async.wait_group 0;\n" ::: "memory")

__device__ __forceinline__ uint32_t sw128(uint32_t off) { return off ^ ((off >> 3) & 0x70); }

__device__ __forceinline__ void ldsm_x4(uint32_t& r0, uint32_t& r1, uint32_t& r2, uint32_t& r3,
                                        uint32_t addr) {
    asm volatile("ldmatrix.sync.aligned.m8n8.x4.shared.b16 {%0,%1,%2,%3}, [%4];"
                 : "=r"(r0), "=r"(r1), "=r"(r2), "=r"(r3) : "r"(addr));
}
__device__ __forceinline__ void mma_f16(float& c0, float& c1, float& c2, float& c3,
                                        uint32_t a0, uint32_t a1, uint32_t a2, uint32_t a3,
                                        uint32_t b0, uint32_t b1) {
    asm volatile("mma.sync.aligned.m16n8k16.row.col.f32.f16.f16.f32 "
                 "{%0,%1,%2,%3}, {%4,%5,%6,%7}, {%8,%9}, {%0,%1,%2,%3};"
                 : "+f"(c0), "+f"(c1), "+f"(c2), "+f"(c3)
                 : "r"(a0), "r"(a1), "r"(a2), "r"(a3), "r"(b0), "r"(b1));
}

// ---------------------------------------------------------------------------
// Convert fp32 -> fp16, 2 independent float4 loads per thread (MLP=2)
// ---------------------------------------------------------------------------
__global__ __launch_bounds__(256) void conv_f16_kernel(
    const float* __restrict__ x, const float* __restrict__ h,
    const float* __restrict__ wih, const float* __restrict__ whh)
{
    int z = blockIdx.z;
    const float* src = (z == 0) ? x : (z == 1) ? h : (z == 2) ? wih : whh;
    __half* dst = (z < 2) ? (g_A2 + (size_t)z * 4096 * 1024)
                          : (g_W2 + (size_t)(z - 2) * 4096 * 1024);
    size_t i0 = (size_t)blockIdx.x * 512 + threadIdx.x;      // 2 float4 per thread
    float4 v0 = *(const float4*)&src[i0 * 4];
    float4 v1 = *(const float4*)&src[(i0 + 256) * 4];
    __half2 a0 = __floats2half2_rn(v0.x, v0.y);
    __half2 a1 = __floats2half2_rn(v0.z, v0.w);
    __half2 b0 = __floats2half2_rn(v1.x, v1.y);
    __half2 b1 = __floats2half2_rn(v1.z, v1.w);
    *(uint2*)&dst[i0 * 4]         = make_uint2(*(uint32_t*)&a0, *(uint32_t*)&a1);
    *(uint2*)&dst[(i0 + 256) * 4] = make_uint2(*(uint32_t*)&b0, *(uint32_t*)&b1);
}

// ---------------------------------------------------------------------------
// fp16 NT GEMM via mma.sync: C[m,n] = sum_k A[m,k]*B[n,k], M=N=4096, K=1024.
// CTA 128x256, BK=64, 4-stage smem, chunk-pair pipeline (one sync / 2 chunks).
// 8 warps: 2(m) x 4(n), warp tile 64x64. blockIdx.z -> (x,w_ih)/(h,w_hh).
// Output stored as fp16 (halves epilogue + epi traffic).
// ---------------------------------------------------------------------------
#define BM 128
#define BN 256
#define NCHUNK 16                     // 1024 / 64
#define ROW_BYTES 2048                // 1024 fp16 per row
#define A_BYTES (BM * 128)            // 16 KB
#define B_BYTES (BN * 128)            // 32 KB
#define STAGE_BYTES (A_BYTES + B_BYTES)
#define NSTAGE 4
#define SMEM_DYN (NSTAGE * STAGE_BYTES + 1024)   // 193 KB

__device__ __forceinline__ void load_chunk(uint32_t aBase, uint32_t bBase,
                                           const char* Ag, const char* Bg,
                                           int m0, int n0, int kc, int tid)
{
#pragma unroll
    for (int i = 0; i < 4; i++) {                 // A: 128 rows x 8 segs = 1024
        int idx = tid + i * 256;
        int row = idx >> 3;
        int seg = idx & 7;
        uint32_t soff = sw128((uint32_t)(row * 128 + seg * 16));
        cp_async16(aBase + soff, Ag + (size_t)(m0 + row) * ROW_BYTES + kc * 128 + seg * 16);
    }
#pragma unroll
    for (int i = 0; i < 8; i++) {                 // B: 256 rows x 8 segs = 2048
        int idx = tid + i * 256;
        int row = idx >> 3;
        int seg = idx & 7;
        uint32_t soff = sw128((uint32_t)(row * 128 + seg * 16));
        cp_async16(bBase + soff, Bg + (size_t)(n0 + row) * ROW_BYTES + kc * 128 + seg * 16);
    }
}

__global__ __launch_bounds__(256, 1) void gemm_mma_kernel()
{
    extern __shared__ char dynsmem[];

    const int tid  = threadIdx.x;
    const int wid  = tid >> 5;
    const int lane = tid & 31;
    const int z  = blockIdx.z;
    const int m0 = blockIdx.y * BM;
    const int n0 = blockIdx.x * BN;

    const char* Ag = (const char*)(g_A2 + (size_t)z * 4096 * 1024);
    const char* Bg = (const char*)(g_W2 + (size_t)z * 4096 * 1024);
    __half* C = g_pre + (size_t)z * 4096 * 4096;

    const int warp_m = wid & 1;
    const int warp_n = wid >> 1;

    uint32_t base = (smem_u32(dynsmem) + 1023u) & ~1023u;

    // per-lane ldmatrix address components (within tile, pre-swizzle)
    const int ar = warp_m * 64 + (lane & 7) + (((lane >> 3) & 1) << 3);
    const int ah = (lane >> 4) & 1;
    const int br = warp_n * 64 + (lane & 7) + (((lane >> 4) & 1) << 3);
    const int bh = (lane >> 3) & 1;

    float acc[4][8][4];
#pragma unroll
    for (int mi = 0; mi < 4; mi++)
#pragma unroll
        for (int oc = 0; oc < 8; oc++)
#pragma unroll
            for (int q = 0; q < 4; q++) acc[mi][oc][q] = 0.0f;

    // prologue: chunks 0,1 into stages 0,1
    load_chunk(base,               base + A_BYTES,               Ag, Bg, m0, n0, 0, tid);
    load_chunk(base + STAGE_BYTES, base + STAGE_BYTES + A_BYTES, Ag, Bg, m0, n0, 1, tid);
    CP_COMMIT();

    for (int c = 0; c < NCHUNK; c += 2) {
        CP_WAIT0();                    // chunks c, c+1 landed
        __syncthreads();               // all warps done reading chunks c-2, c-1

        // refill freed stages with chunks c+2, c+3; overlaps the 8-ks compute
        if (c + 2 < NCHUNK) {
            load_chunk(base + (uint32_t)((c + 2) & 3) * STAGE_BYTES,
                       base + (uint32_t)((c + 2) & 3) * STAGE_BYTES + A_BYTES,
                       Ag, Bg, m0, n0, c + 2, tid);
            load_chunk(base + (uint32_t)((c + 3) & 3) * STAGE_BYTES,
                       base + (uint32_t)((c + 3) & 3) * STAGE_BYTES + A_BYTES,
                       Ag, Bg, m0, n0, c + 3, tid);
            CP_COMMIT();
        }

        // compute chunks c and c+1: 8 straight-line ks steps, no barriers
#pragma unroll
        for (int half = 0; half < 2; half++) {
            const uint32_t stg = base + (uint32_t)((c + half) & 3) * STAGE_BYTES;
            const uint32_t aB = stg;
            const uint32_t bB = stg + A_BYTES;
#pragma unroll
            for (int ks = 0; ks < 4; ks++) {
                uint32_t a[4][4], b[4][4];
#pragma unroll
                for (int mi = 0; mi < 4; mi++) {
                    uint32_t off = (uint32_t)((ar + mi * 16) * 128 + ks * 32 + ah * 16);
                    ldsm_x4(a[mi][0], a[mi][1], a[mi][2], a[mi][3], aB + sw128(off));
                }
#pragma unroll
                for (int pi = 0; pi < 4; pi++) {
                    uint32_t off = (uint32_t)((br + pi * 16) * 128 + ks * 32 + bh * 16);
                    ldsm_x4(b[pi][0], b[pi][1], b[pi][2], b[pi][3], bB + sw128(off));
                }
#pragma unroll
                for (int mi = 0; mi < 4; mi++)
#pragma unroll
                    for (int oc = 0; oc < 8; oc++) {
                        uint32_t b0 = b[oc >> 1][(oc & 1) * 2];
                        uint32_t b1 = b[oc >> 1][(oc & 1) * 2 + 1];
                        mma_f16(acc[mi][oc][0], acc[mi][oc][1], acc[mi][oc][2], acc[mi][oc][3],
                                a[mi][0], a[mi][1], a[mi][2], a[mi][3], b0, b1);
                    }
            }
        }
    }

    // epilogue: fp16 streaming stores. Each quad lane writes a half2 (cols c,c+1);
    // 4 lanes of a quad cover 16B contiguous -> full sectors.
    const int rbase = m0 + warp_m * 64 + (lane >> 2);
    const int cbase = n0 + warp_n * 64 + (lane & 3) * 2;
#pragma unroll
    for (int mi = 0; mi < 4; mi++) {
#pragma unroll
        for (int oc = 0; oc < 8; oc++) {
            size_t r0 = (size_t)(rbase + mi * 16) * 4096 + cbase + oc * 8;
            size_t r1 = (size_t)(rbase + mi * 16 + 8) * 4096 + cbase + oc * 8;
            __half2 h0 = __floats2half2_rn(acc[mi][oc][0], acc[mi][oc][1]);
            __half2 h1 = __floats2half2_rn(acc[mi][oc][2], acc[mi][oc][3]);
            __stcs((__half2*)&C[r0], h0);
            __stcs((__half2*)&C[r1], h1);
        }
    }
}

// ---------------------------------------------------------------------------
// block reductions (256 threads), single __syncthreads each
// ---------------------------------------------------------------------------
__device__ __forceinline__ void blockReduce16(float* v)   // v[16], result in all threads
{
    __shared__ float sb16[8][16];
    const unsigned m = 0xffffffffu;
#pragma unroll
    for (int o = 16; o > 0; o >>= 1)
#pragma unroll
        for (int k = 0; k < 16; k++) v[k] += __shfl_down_sync(m, v[k], o);
    int lane = threadIdx.x & 31, warp = threadIdx.x >> 5;
    if (lane == 0)
#pragma unroll
        for (int k = 0; k < 16; k++) sb16[warp][k] = v[k];
    __syncthreads();
#pragma unroll
    for (int k = 0; k < 16; k++) {
        float s = 0.f;
#pragma unroll
        for (int w = 0; w < 8; w++) s += sb16[w][k];
        v[k] = s;
    }
}

__device__ __forceinline__ float2 blockReduce2(float2 v)
{
    __shared__ float sb2[8][2];
    const unsigned m = 0xffffffffu;
#pragma unroll
    for (int o = 16; o > 0; o >>= 1) {
        v.x += __shfl_down_sync(m, v.x, o);
        v.y += __shfl_down_sync(m, v.y, o);
    }
    int lane = threadIdx.x & 31, warp = threadIdx.x >> 5;
    __syncthreads();
    if (lane == 0) { sb2[warp][0] = v.x; sb2[warp][1] = v.y; }
    __syncthreads();
    float2 r = make_float2(0.f, 0.f);
#pragma unroll
    for (int w = 0; w < 8; w++) { r.x += sb2[w][0]; r.y += sb2[w][1]; }
    return r;
}

__device__ __forceinline__ float sigf(float x) { return 1.0f / (1.0f + expf(-x)); }

// ---------------------------------------------------------------------------
// Fused LN + gates + cell update. One CTA (256 thr) per batch row.
// Reads fp16 pre-activations (half the traffic of fp32).
// ---------------------------------------------------------------------------
__global__ __launch_bounds__(256) void lstm_epi_kernel(
    const float* __restrict__ cin, const float* __restrict__ b_ih,
    const float* __restrict__ gamma, const float* __restrict__ beta,
    float* __restrict__ out)
{
    const int H = 1024, B = 4096;
    const int b = blockIdx.x;
    const int j = threadIdx.x * 4;
    const float invH = 1.0f / (float)H;

    const __half* pih = g_pre + (size_t)b * 4096;
    const __half* phh = g_pre + (size_t)4096 * 4096 + (size_t)b * 4096;

    float vi[4][4], vh[4][4];
    float part[16];

#pragma unroll
    for (int g = 0; g < 4; g++) {
        uint2 ti = __ldcs((const uint2*)&pih[g * H + j]);   // 4 halves
        uint2 th = __ldcs((const uint2*)&phh[g * H + j]);
        float2 t0 = __half22float2(*(__half2*)&ti.x);
        float2 t1 = __half22float2(*(__half2*)&ti.y);
        float2 u0 = __half22float2(*(__half2*)&th.x);
        float2 u1 = __half22float2(*(__half2*)&th.y);
        vi[g][0] = t0.x; vi[g][1] = t0.y; vi[g][2] = t1.x; vi[g][3] = t1.y;
        vh[g][0] = u0.x; vh[g][1] = u0.y; vh[g][2] = u1.x; vh[g][3] = u1.y;
        part[g * 4 + 0] = vi[g][0] + vi[g][1] + vi[g][2] + vi[g][3];
        part[g * 4 + 1] = vi[g][0]*vi[g][0] + vi[g][1]*vi[g][1] + vi[g][2]*vi[g][2] + vi[g][3]*vi[g][3];
        part[g * 4 + 2] = vh[g][0] + vh[g][1] + vh[g][2] + vh[g][3];
        part[g * 4 + 3] = vh[g][0]*vh[g][0] + vh[g][1]*vh[g][1] + vh[g][2]*vh[g][2] + vh[g][3]*vh[g][3];
    }

    blockReduce16(part);     // one fused reduction for all 4 gates

    float gate[4][4];
#pragma unroll
    for (int g = 0; g < 4; g++) {
        float mi = part[g * 4 + 0] * invH;
        float ri = rsqrtf(part[g * 4 + 1] * invH - mi * mi + LN_EPS);
        float mh = part[g * 4 + 2] * invH;
        float rh = rsqrtf(part[g * 4 + 3] * invH - mh * mh + LN_EPS);

        float4 gi4 = *(const float4*)&gamma[(2 * g) * H + j];
        float4 bi4 = *(const float4*)&beta [(2 * g) * H + j];
        float4 gh4 = *(const float4*)&gamma[(2 * g + 1) * H + j];
        float4 bh4 = *(const float4*)&beta [(2 * g + 1) * H + j];
        float4 bb4 = *(const float4*)&b_ih [g * H + j];
        float gi[4] = { gi4.x, gi4.y, gi4.z, gi4.w };
        float bi[4] = { bi4.x, bi4.y, bi4.z, bi4.w };
        float gh[4] = { gh4.x, gh4.y, gh4.z, gh4.w };
        float bh[4] = { bh4.x, bh4.y, bh4.z, bh4.w };
        float bb[4] = { bb4.x, bb4.y, bb4.z, bb4.w };

#pragma unroll
        for (int u = 0; u < 4; u++)
            gate[g][u] = gi[u] * (vi[g][u] - mi) * ri + bi[u]
                       + gh[u] * (vh[g][u] - mh) * rh + bh[u]
                       + bb[u];
    }

    float4 cv4 = *(const float4*)&cin[(size_t)b * H + j];
    float cv[4] = { cv4.x, cv4.y, cv4.z, cv4.w };
    float cn[4];
#pragma unroll
    for (int u = 0; u < 4; u++)
        cn[u] = sigf(gate[1][u]) * cv[u] + sigf(gate[0][u]) * tanhf(gate[2][u]);

    float2 pc;
    pc.x = cn[0] + cn[1] + cn[2] + cn[3];
    pc.y = cn[0]*cn[0] + cn[1]*cn[1] + cn[2]*cn[2] + cn[3]*cn[3];
    float2 tc = blockReduce2(pc);
    float mc = tc.x * invH;
    float rc = rsqrtf(tc.y * invH - mc * mc + LN_EPS);

    float4 g84 = *(const float4*)&gamma[8 * H + j];
    float4 b84 = *(const float4*)&beta [8 * H + j];
    float g8[4] = { g84.x, g84.y, g84.z, g84.w };
    float b8[4] = { b84.x, b84.y, b84.z, b84.w };

    float hn[4];
#pragma unroll
    for (int u = 0; u < 4; u++) {
        float lnc = g8[u] * (cn[u] - mc) * rc + b8[u];
        hn[u] = sigf(gate[3][u]) * tanhf(lnc);
    }

    *(float4*)&out[(size_t)b * H + j] = make_float4(hn[0], hn[1], hn[2], hn[3]);
    *(float4*)&out[(size_t)B * H + (size_t)b * H + j] = make_float4(cn[0], cn[1], cn[2], cn[3]);
}

// ---------------------------------------------------------------------------
// inputs (metadata order): x, h, c, w_ih, w_hh, b_ih, ln_gamma, ln_beta, time
// ---------------------------------------------------------------------------
extern "C" void kernel_launch(void* const* d_in, const int* in_sizes, int n_in,
                              void* d_out, int out_size)
{
    const float* x     = (const float*)d_in[0];
    const float* h     = (const float*)d_in[1];
    const float* c     = (const float*)d_in[2];
    const float* w_ih  = (const float*)d_in[3];
    const float* w_hh  = (const float*)d_in[4];
    const float* b_ih  = (const float*)d_in[5];
    const float* gamma = (const float*)d_in[6];
    const float* beta  = (const float*)d_in[7];
    float* out = (float*)d_out;

    cudaFuncSetAttribute(gemm_mma_kernel,
                         cudaFuncAttributeMaxDynamicSharedMemorySize, SMEM_DYN);

    conv_f16_kernel<<<dim3(2048, 1, 4), 256>>>(x, h, w_ih, w_hh);
    gemm_mma_kernel<<<dim3(16, 32, 2), 256, SMEM_DYN>>>();
    lstm_epi_kernel<<<4096, 256>>>(c, b_ih, gamma, beta, out);
}